// round 11
// baseline (speedup 1.0000x reference)
#include <cuda_runtime.h>
#include <cuda_bf16.h>
#include <cuda_fp16.h>
#include <math.h>

#define N_NODES 10000
#define N_EDGES 160000
#define N_GRAPH 64
#define HID     128
#define H2      256
#define N_LAYER 14
#define BM      72            // rows per fused-layer block; grid = 139 <= 148 SMs (one wave)
#define FTHREADS 384          // 12 warps, 3 per SMSP

// ---------------- device scratch (no allocations allowed) ----------------
__device__ float   g_h[N_NODES * HID];
__device__ float   g_r[N_NODES * HID];
__device__ float   g_rnorm[N_NODES];
__device__ __half2 g_PQ[N_NODES * HID];   // (P,Q) fp16 pair per feature
__device__ int     g_deg[N_NODES];
__device__ int     g_rowptr[N_NODES + 1];
__device__ int     g_cursor[N_NODES];
__device__ int     g_col[N_EDGES];
__device__ float   g_gsum[N_GRAPH * HID];
__device__ float   g_cnt[N_GRAPH];

typedef unsigned long long ull;

// ---------------- helpers ----------------
__device__ __forceinline__ ull pack2(float lo, float hi) {
    ull r;
    asm("mov.b64 %0, {%1,%2};" : "=l"(r) : "f"(lo), "f"(hi));
    return r;
}
__device__ __forceinline__ void unpack2(ull v, float& lo, float& hi) {
    asm("mov.b64 {%0,%1}, %2;" : "=f"(lo), "=f"(hi) : "l"(v));
}
#define FMA_F32X2(d, a, b, c) \
    asm("fma.rn.f32x2 %0, %1, %2, %3;" : "=l"(d) : "l"(a), "l"(b), "l"(c))

__device__ __forceinline__ void cp_async16(float* smem_dst, const float* gmem_src) {
    unsigned sa = (unsigned)__cvta_generic_to_shared(smem_dst);
    asm volatile("cp.async.cg.shared.global [%0], [%1], 16;" :: "r"(sa), "l"(gmem_src));
}
#define CP_COMMIT() asm volatile("cp.async.commit_group;")
#define CP_WAIT0()  asm volatile("cp.async.wait_group 0;")

// predicated 16B global load: zero when pred==0, NO memory traffic when off.
__device__ __forceinline__ uint4 ldg_pq_pred(const __half2* p, unsigned pred) {
    uint4 u;
    asm volatile(
        "{\n\t.reg .pred q;\n\t"
        "setp.ne.u32 q, %4, 0;\n\t"
        "mov.u32 %0, 0;\n\tmov.u32 %1, 0;\n\tmov.u32 %2, 0;\n\tmov.u32 %3, 0;\n\t"
        "@q ld.global.nc.v4.u32 {%0,%1,%2,%3}, [%5];\n\t}"
        : "=r"(u.x), "=r"(u.y), "=r"(u.z), "=r"(u.w)
        : "r"(pred), "l"(p));
    return u;
}

__device__ __forceinline__ float warpSum(float v) {
    #pragma unroll
    for (int o = 16; o; o >>= 1) v += __shfl_xor_sync(0xffffffffu, v, o);
    return v;
}
__device__ __forceinline__ float blockSum(float v, float* s) {
    #pragma unroll
    for (int o = 16; o; o >>= 1) v += __shfl_down_sync(0xffffffffu, v, o);
    __syncthreads();
    if ((threadIdx.x & 31) == 0) s[threadIdx.x >> 5] = v;
    __syncthreads();
    int nw = blockDim.x >> 5;
    float t = 0.f;
    for (int i = 0; i < nw; i++) t += s[i];
    return t;
}

// pack (p,q) float pairs into half2 lanes of a uint4
__device__ __forceinline__ uint4 packPQ(float4 pp, float4 qq) {
    __half2 h0 = __floats2half2_rn(pp.x, qq.x);
    __half2 h1 = __floats2half2_rn(pp.y, qq.y);
    __half2 h2 = __floats2half2_rn(pp.z, qq.z);
    __half2 h3 = __floats2half2_rn(pp.w, qq.w);
    uint4 u;
    u.x = *(unsigned*)&h0; u.y = *(unsigned*)&h1;
    u.z = *(unsigned*)&h2; u.w = *(unsigned*)&h3;
    return u;
}

// ---------------- zero (CSR counts + pool) ----------------
__global__ void zero_kernel() {
    int i = blockIdx.x * blockDim.x + threadIdx.x;
    if (i < N_NODES) g_deg[i] = 0;
    if (i < N_GRAPH * HID) g_gsum[i] = 0.f;
    if (i < N_GRAPH) g_cnt[i] = 0.f;
}
__global__ void csr_count_kernel(const int* __restrict__ ei) {
    int e = blockIdx.x * blockDim.x + threadIdx.x;
    if (e < N_EDGES) atomicAdd(&g_deg[ei[N_EDGES + e]], 1);
}
__global__ void scan_kernel() {
    __shared__ int s[1024];
    const int CH = 10;
    int t = threadIdx.x;
    int base = t * CH;
    int local[CH];
    int sum = 0;
    #pragma unroll
    for (int j = 0; j < CH; j++) {
        int idx = base + j;
        int v = (idx < N_NODES) ? g_deg[idx] : 0;
        local[j] = sum;
        sum += v;
    }
    s[t] = sum;
    __syncthreads();
    for (int off = 1; off < 1024; off <<= 1) {
        int v = (t >= off) ? s[t - off] : 0;
        __syncthreads();
        s[t] += v;
        __syncthreads();
    }
    int offset = (t > 0) ? s[t - 1] : 0;
    #pragma unroll
    for (int j = 0; j < CH; j++) {
        int idx = base + j;
        if (idx < N_NODES) {
            g_rowptr[idx] = offset + local[j];
            g_cursor[idx] = offset + local[j];
        }
    }
    if (t == 1023) g_rowptr[N_NODES] = s[1023];
}
__global__ void csr_fill_kernel(const int* __restrict__ ei) {
    int e = blockIdx.x * blockDim.x + threadIdx.x;
    if (e < N_EDGES) {
        int d = ei[N_EDGES + e];
        int p = atomicAdd(&g_cursor[d], 1);
        g_col[p] = ei[e];
    }
}

// ---------------- encoder GEMM: C = A@B + bias ----------------
__global__ __launch_bounds__(256) void gemm_kernel(
    const float* __restrict__ A, const float* __restrict__ B,
    const float* __restrict__ bias, float* __restrict__ Cout,
    int M, int N, int K)
{
    __shared__ float As[16][64];
    __shared__ float Bs[16][128];
    int tid = threadIdx.x;
    int bm = blockIdx.y * 64;
    int bn = blockIdx.x * 128;
    int tr = tid >> 5;
    int tc = tid & 31;
    int row0 = tr * 8, col0 = tc * 4;

    ull acc[8][2];
    #pragma unroll
    for (int i = 0; i < 8; i++) { acc[i][0] = 0ull; acc[i][1] = 0ull; }

    int a_row = tid >> 2;
    int a_col = (tid & 3) * 4;

    for (int k0 = 0; k0 < K; k0 += 16) {
        float4 av = make_float4(0.f, 0.f, 0.f, 0.f);
        int gr = bm + a_row;
        if (gr < M) av = *(const float4*)&A[(size_t)gr * K + k0 + a_col];
        As[a_col + 0][a_row] = av.x;
        As[a_col + 1][a_row] = av.y;
        As[a_col + 2][a_row] = av.z;
        As[a_col + 3][a_row] = av.w;
        #pragma unroll
        for (int i = 0; i < 2; i++) {
            int f = tid + i * 256;
            int br = f >> 5, bc = (f & 31) * 4;
            *(float4*)&Bs[br][bc] = *(const float4*)&B[(size_t)(k0 + br) * N + bn + bc];
        }
        __syncthreads();
        #pragma unroll
        for (int k = 0; k < 16; k++) {
            float a[8];
            *(float4*)&a[0] = *(const float4*)&As[k][row0];
            *(float4*)&a[4] = *(const float4*)&As[k][row0 + 4];
            ulonglong2 bb = *(const ulonglong2*)&Bs[k][col0];
            #pragma unroll
            for (int i = 0; i < 8; i++) {
                ull aa = pack2(a[i], a[i]);
                FMA_F32X2(acc[i][0], aa, bb.x, acc[i][0]);
                FMA_F32X2(acc[i][1], aa, bb.y, acc[i][1]);
            }
        }
        __syncthreads();
    }

    int c = bn + col0;
    float4 bv = *(const float4*)&bias[c];
    #pragma unroll
    for (int i = 0; i < 8; i++) {
        int r = bm + row0 + i;
        if (r >= M) break;
        float v0, v1, v2, v3;
        unpack2(acc[i][0], v0, v1);
        unpack2(acc[i][1], v2, v3);
        float4 o = make_float4(v0 + bv.x, v1 + bv.y, v2 + bv.z, v3 + bv.w);
        *(float4*)&Cout[(size_t)r * N + c] = o;
    }
}

// ---------------- per-node pre kernel (layer 0 only) ----------------
__global__ __launch_bounds__(128) void node_pre_kernel(
    const float* __restrict__ ln_g, const float* __restrict__ ln_b,
    const float* __restrict__ tptr, int li)
{
    __shared__ float s[8];
    int n = blockIdx.x, f = threadIdx.x;
    float x = g_h[n * HID + f];
    float mu = blockSum(x, s) * (1.f / HID);
    float d = x - mu;
    float var = blockSum(d * d, s) * (1.f / HID);
    float y = d * rsqrtf(var + 1e-5f) * ln_g[li * HID + f] + ln_b[li * HID + f];
    float r = (y > 0.f) ? y : 0.01f * y;
    g_r[n * HID + f] = r;
    float nrm2 = blockSum(r * r, s);
    if (f == 0) g_rnorm[n] = sqrtf(nrm2);
    float t = tptr[li];
    float m = fmaxf(y, 0.f) + 1e-7f;
    float q = expf(m * t);
    g_PQ[n * HID + f] = __floats2half2_rn(m * q, q);
}

// ---------------- fused layer: aggregate + GEMM1 + LN+ReLU + GEMM2 + residual + pre
// BM=72, 384 threads (12 warps, 3/SMSP). Warp w owns rows 6w..6w+5. grid 139.
#define Z1_STRIDE 260
#define HS_STRIDE 132
#define ASTRIDE   76
#define AS_OFF    (BM * Z1_STRIDE)               // 18720
#define BS_OFF    (AS_OFF + 2 * 16 * ASTRIDE)    // 21152
#define FUSED_SMEM ((BS_OFF + 2 * 16 * 256) * 4) // 117376 bytes

__global__ void __launch_bounds__(FTHREADS) fused_layer_kernel(
    const float* __restrict__ W1, const float* __restrict__ b1,
    const float* __restrict__ mg, const float* __restrict__ mb,
    const float* __restrict__ W2, const float* __restrict__ b2,
    const float* __restrict__ ln_g, const float* __restrict__ ln_b,
    const float* __restrict__ tptr, const float* __restrict__ scptr,
    int li, int do_pre,
    float* __restrict__ hb, float* __restrict__ rb,
    __half2* __restrict__ pqb, float* __restrict__ rnb)
{
    extern __shared__ float sm[];
    float* outs = sm;                // [72][132]  (aliases z1s region; dead before z1 writes)
    float* z1s  = sm;                // [72][260]
    float* As0  = sm + AS_OFF;       // double buffer [2][16][76]
    float* Bs0  = sm + BS_OFF;       // double buffer [2][16][256] (C: [2][16][128])

    const int tid  = threadIdx.x;
    const int warp = tid >> 5, lane = tid & 31;
    const int bm   = blockIdx.x * BM;
    const int row0 = warp * 6;       // 6 rows per warp
    const int c0   = lane * 4;

    const float* Wl1 = W1 + (size_t)li * HID * H2;

    // issue first W1 tile prefetch immediately — overlaps the aggregation phase
    {
        #pragma unroll
        for (int i = 0; i < 3; i++) {
            int idx = tid + i * FTHREADS;
            if (idx < 1024) cp_async16(Bs0 + idx * 4, Wl1 + idx * 4);
        }
        CP_COMMIT();
    }

    // ======== Phase 0: softmax-aggregate, row-interleaved for MLP ========
    {
        float scv = scptr[li];
        int ep[6], en[6];
        float4 num[6], den[6];
        #pragma unroll
        for (int i = 0; i < 6; i++) {
            int n = bm + row0 + i;
            if (n < N_NODES) {
                ep[i] = g_rowptr[n];
                en[i] = g_rowptr[n + 1];
            } else {
                ep[i] = 0; en[i] = 0;
            }
            num[i] = make_float4(0.f, 0.f, 0.f, 0.f);
            den[i] = make_float4(0.f, 0.f, 0.f, 0.f);
        }
        int iters = 0;
        #pragma unroll
        for (int i = 0; i < 6; i++) {
            int it = (en[i] - ep[i] + 1) >> 1;
            if (it > iters) iters = it;
        }

        for (int it = 0; it < iters; it++) {
            // batch 1: all column indices (MLP 12)
            int ca[6], cb[6];
            unsigned pa[6], pb[6];
            #pragma unroll
            for (int i = 0; i < 6; i++) {
                pa[i] = (unsigned)(ep[i] < en[i]);
                pb[i] = (unsigned)(ep[i] + 1 < en[i]);
                int i0 = min(ep[i], N_EDGES - 1);
                int i1 = min(ep[i] + 1, N_EDGES - 1);
                ca[i] = __ldg(&g_col[i0]);
                cb[i] = __ldg(&g_col[i1]);
            }
            // batch 2: all PQ gathers (MLP 12), predicated off => no traffic
            uint4 ua[6], ub[6];
            #pragma unroll
            for (int i = 0; i < 6; i++) {
                ua[i] = ldg_pq_pred(&g_PQ[(size_t)ca[i] * HID + c0], pa[i]);
                ub[i] = ldg_pq_pred(&g_PQ[(size_t)cb[i] * HID + c0], pb[i]);
            }
            // batch 3: accumulate (zeros when predicated off)
            #pragma unroll
            for (int i = 0; i < 6; i++) {
                float2 t;
                t = __half22float2(*(__half2*)&ua[i].x); num[i].x += t.x; den[i].x += t.y;
                t = __half22float2(*(__half2*)&ua[i].y); num[i].y += t.x; den[i].y += t.y;
                t = __half22float2(*(__half2*)&ua[i].z); num[i].z += t.x; den[i].z += t.y;
                t = __half22float2(*(__half2*)&ua[i].w); num[i].w += t.x; den[i].w += t.y;
                t = __half22float2(*(__half2*)&ub[i].x); num[i].x += t.x; den[i].x += t.y;
                t = __half22float2(*(__half2*)&ub[i].y); num[i].y += t.x; den[i].y += t.y;
                t = __half22float2(*(__half2*)&ub[i].z); num[i].z += t.x; den[i].z += t.y;
                t = __half22float2(*(__half2*)&ub[i].w); num[i].w += t.x; den[i].w += t.y;
                ep[i] += 2;
            }
        }

        // finalize: softmax ratio + MessageNorm + residual -> outs
        #pragma unroll
        for (int i = 0; i < 6; i++) {
            int row = row0 + i;
            int n = bm + row;
            int nc = (n < N_NODES) ? n : 0;
            float4 agg;
            agg.x = num[i].x / (den[i].x + 1e-16f);
            agg.y = num[i].y / (den[i].y + 1e-16f);
            agg.z = num[i].z / (den[i].z + 1e-16f);
            agg.w = num[i].w / (den[i].w + 1e-16f);
            float n2 = warpSum(agg.x * agg.x + agg.y * agg.y
                             + agg.z * agg.z + agg.w * agg.w);
            float inv = 1.f / fmaxf(sqrtf(n2), 1e-12f);
            float coef = inv * rnb[nc] * scv;
            float4 rv = *(const float4*)&rb[(size_t)nc * HID + c0];
            float4 o = make_float4(rv.x + agg.x * coef, rv.y + agg.y * coef,
                                   rv.z + agg.z * coef, rv.w + agg.w * coef);
            *(float4*)&outs[row * HS_STRIDE + c0] = o;
        }
    }
    __syncthreads();   // outs complete for all rows

    // ======== Stage A: z1 = outs @ W1 + b1  (72x256, K=128) ========
    ull acc[6][4];
    #pragma unroll
    for (int i = 0; i < 6; i++)
        #pragma unroll
        for (int j = 0; j < 4; j++) acc[i][j] = 0ull;

    const int ar = tid >> 2;          // 0..95 (only <72 active)
    const int ac = (tid & 3) * 4;     // 0,4,8,12
    const bool aact = (ar < BM);

    float4 av = make_float4(0.f, 0.f, 0.f, 0.f);
    if (aact) av = *(const float4*)&outs[ar * HS_STRIDE + ac];

    int buf = 0;
    for (int k0 = 0; k0 < HID; k0 += 16) {
        float* Asb = As0 + buf * (16 * ASTRIDE);
        float* Bsb = Bs0 + buf * (16 * 256);
        if (aact) {
            Asb[(ac + 0) * ASTRIDE + ar] = av.x;
            Asb[(ac + 1) * ASTRIDE + ar] = av.y;
            Asb[(ac + 2) * ASTRIDE + ar] = av.z;
            Asb[(ac + 3) * ASTRIDE + ar] = av.w;
        }
        CP_WAIT0();
        __syncthreads();
        if (k0 + 16 < HID) {
            if (aact) av = *(const float4*)&outs[ar * HS_STRIDE + k0 + 16 + ac];
            float* dst = Bs0 + (buf ^ 1) * (16 * 256);
            const float* srcb = Wl1 + (size_t)(k0 + 16) * H2;
            #pragma unroll
            for (int i = 0; i < 3; i++) {
                int idx = tid + i * FTHREADS;
                if (idx < 1024) cp_async16(dst + idx * 4, srcb + idx * 4);
            }
            CP_COMMIT();
        }
        #pragma unroll
        for (int k = 0; k < 16; k++) {
            const float* Ak = Asb + k * ASTRIDE;
            ull r01 = *(const ull*)&Ak[row0];
            ull r23 = *(const ull*)&Ak[row0 + 2];
            ull r45 = *(const ull*)&Ak[row0 + 4];
            const float* Bk = Bsb + k * 256;
            ulonglong2 bA = *(const ulonglong2*)&Bk[c0];
            ulonglong2 bB = *(const ulonglong2*)&Bk[128 + c0];
            float a[6];
            unpack2(r01, a[0], a[1]);
            unpack2(r23, a[2], a[3]);
            unpack2(r45, a[4], a[5]);
            #pragma unroll
            for (int i = 0; i < 6; i++) {
                ull aa = pack2(a[i], a[i]);
                FMA_F32X2(acc[i][0], aa, bA.x, acc[i][0]);
                FMA_F32X2(acc[i][1], aa, bA.y, acc[i][1]);
                FMA_F32X2(acc[i][2], aa, bB.x, acc[i][2]);
                FMA_F32X2(acc[i][3], aa, bB.y, acc[i][3]);
            }
        }
        buf ^= 1;
    }
    __syncthreads();   // outs fully consumed; z1s region free to overwrite

    // write z1 tile (+bias) to smem
    {
        float4 bvA = *(const float4*)&b1[(size_t)li * H2 + c0];
        float4 bvB = *(const float4*)&b1[(size_t)li * H2 + 128 + c0];
        #pragma unroll
        for (int i = 0; i < 6; i++) {
            int row = row0 + i;
            float v0, v1, v2, v3;
            unpack2(acc[i][0], v0, v1);
            unpack2(acc[i][1], v2, v3);
            float4 oA = make_float4(v0 + bvA.x, v1 + bvA.y, v2 + bvA.z, v3 + bvA.w);
            unpack2(acc[i][2], v0, v1);
            unpack2(acc[i][3], v2, v3);
            float4 oB = make_float4(v0 + bvB.x, v1 + bvB.y, v2 + bvB.z, v3 + bvB.w);
            *(float4*)&z1s[row * Z1_STRIDE + c0]       = oA;
            *(float4*)&z1s[row * Z1_STRIDE + 128 + c0] = oB;
        }
    }

    // ======== LayerNorm(256) + ReLU in smem (rows are warp-local) ========
    {
        float4 gA = *(const float4*)&mg[(size_t)li * H2 + c0];
        float4 gB = *(const float4*)&mg[(size_t)li * H2 + 128 + c0];
        float4 bA = *(const float4*)&mb[(size_t)li * H2 + c0];
        float4 bB = *(const float4*)&mb[(size_t)li * H2 + 128 + c0];
        #pragma unroll
        for (int i = 0; i < 6; i++) {
            float* rp = &z1s[(row0 + i) * Z1_STRIDE];
            float4 vA = *(const float4*)&rp[c0];
            float4 vB = *(const float4*)&rp[128 + c0];
            float s1 = (vA.x + vA.y) + (vA.z + vA.w) + (vB.x + vB.y) + (vB.z + vB.w);
            float s2 = vA.x * vA.x + vA.y * vA.y + vA.z * vA.z + vA.w * vA.w
                     + vB.x * vB.x + vB.y * vB.y + vB.z * vB.z + vB.w * vB.w;
            s1 = warpSum(s1);
            s2 = warpSum(s2);
            float mu  = s1 * (1.f / H2);
            float var = s2 * (1.f / H2) - mu * mu;
            float is  = rsqrtf(var + 1e-5f);
            vA.x = fmaxf((vA.x - mu) * is * gA.x + bA.x, 0.f);
            vA.y = fmaxf((vA.y - mu) * is * gA.y + bA.y, 0.f);
            vA.z = fmaxf((vA.z - mu) * is * gA.z + bA.z, 0.f);
            vA.w = fmaxf((vA.w - mu) * is * gA.w + bA.w, 0.f);
            vB.x = fmaxf((vB.x - mu) * is * gB.x + bB.x, 0.f);
            vB.y = fmaxf((vB.y - mu) * is * gB.y + bB.y, 0.f);
            vB.z = fmaxf((vB.z - mu) * is * gB.z + bB.z, 0.f);
            vB.w = fmaxf((vB.w - mu) * is * gB.w + bB.w, 0.f);
            *(float4*)&rp[c0]       = vA;
            *(float4*)&rp[128 + c0] = vB;
        }
    }
    __syncthreads();

    // ======== Stage C: h' = h + a @ W2 + b2  (72x128, K=256) ========
    ull acc2[6][2];
    #pragma unroll
    for (int i = 0; i < 6; i++) { acc2[i][0] = 0ull; acc2[i][1] = 0ull; }

    const float* Wl2 = W2 + (size_t)li * H2 * HID;
    {
        #pragma unroll
        for (int i = 0; i < 2; i++) {
            int idx = tid + i * FTHREADS;
            if (idx < 512) cp_async16(Bs0 + idx * 4, Wl2 + idx * 4);
        }
        CP_COMMIT();
    }
    buf = 0;
    for (int k0 = 0; k0 < H2; k0 += 16) {
        CP_WAIT0();
        __syncthreads();
        float* Bsb = Bs0 + buf * (16 * 128);
        if (k0 + 16 < H2) {
            float* dst = Bs0 + (buf ^ 1) * (16 * 128);
            const float* srcb = Wl2 + (size_t)(k0 + 16) * HID;
            #pragma unroll
            for (int i = 0; i < 2; i++) {
                int idx = tid + i * FTHREADS;
                if (idx < 512) cp_async16(dst + idx * 4, srcb + idx * 4);
            }
            CP_COMMIT();
        }
        #pragma unroll
        for (int k4 = 0; k4 < 4; k4++) {
            float4 a4[6];
            #pragma unroll
            for (int i = 0; i < 6; i++)
                a4[i] = *(const float4*)&z1s[(row0 + i) * Z1_STRIDE + k0 + k4 * 4];
            #pragma unroll
            for (int kk = 0; kk < 4; kk++) {
                ulonglong2 bb = *(const ulonglong2*)&Bsb[(k4 * 4 + kk) * 128 + c0];
                #pragma unroll
                for (int i = 0; i < 6; i++) {
                    float avv = (kk == 0) ? a4[i].x : (kk == 1) ? a4[i].y
                              : (kk == 2) ? a4[i].z : a4[i].w;
                    ull aa = pack2(avv, avv);
                    FMA_F32X2(acc2[i][0], aa, bb.x, acc2[i][0]);
                    FMA_F32X2(acc2[i][1], aa, bb.y, acc2[i][1]);
                }
            }
        }
        buf ^= 1;
    }
    __syncthreads();

    // epilogue: residual add, write h, stash tile in smem (reuse z1s region)
    float* hs = sm;  // [72][132]
    {
        float4 bv = *(const float4*)&b2[(size_t)li * HID + c0];
        #pragma unroll
        for (int i = 0; i < 6; i++) {
            int row = row0 + i;
            int r = bm + row;
            float v0, v1, v2, v3;
            unpack2(acc2[i][0], v0, v1);
            unpack2(acc2[i][1], v2, v3);
            float4 o = make_float4(v0 + bv.x, v1 + bv.y, v2 + bv.z, v3 + bv.w);
            if (r < N_NODES) {
                float4 hold = *(const float4*)&hb[(size_t)r * HID + c0];
                o.x += hold.x; o.y += hold.y; o.z += hold.z; o.w += hold.w;
                *(float4*)&hb[(size_t)r * HID + c0] = o;
            }
            *(float4*)&hs[row * HS_STRIDE + c0] = o;
        }
    }

    // ======== next-layer node_pre fused (rows warp-local) ========
    if (do_pre) {
        int ln = li + 1;
        float4 gv = *(const float4*)&ln_g[(size_t)ln * HID + c0];
        float4 bb = *(const float4*)&ln_b[(size_t)ln * HID + c0];
        float t = tptr[ln];
        #pragma unroll
        for (int i = 0; i < 6; i++) {
            int row = row0 + i;
            int r = bm + row;
            if (r >= N_NODES) continue;
            float4 v = *(const float4*)&hs[row * HS_STRIDE + c0];
            float s1 = (v.x + v.y) + (v.z + v.w);
            float s2 = v.x * v.x + v.y * v.y + v.z * v.z + v.w * v.w;
            s1 = warpSum(s1);
            s2 = warpSum(s2);
            float mu  = s1 * (1.f / HID);
            float var = s2 * (1.f / HID) - mu * mu;
            float is  = rsqrtf(var + 1e-5f);
            float y0 = (v.x - mu) * is * gv.x + bb.x;
            float y1 = (v.y - mu) * is * gv.y + bb.y;
            float y2 = (v.z - mu) * is * gv.z + bb.z;
            float y3 = (v.w - mu) * is * gv.w + bb.w;
            float4 rr = make_float4((y0 > 0.f) ? y0 : 0.01f * y0,
                                    (y1 > 0.f) ? y1 : 0.01f * y1,
                                    (y2 > 0.f) ? y2 : 0.01f * y2,
                                    (y3 > 0.f) ? y3 : 0.01f * y3);
            float m0 = fmaxf(y0, 0.f) + 1e-7f;
            float m1 = fmaxf(y1, 0.f) + 1e-7f;
            float m2 = fmaxf(y2, 0.f) + 1e-7f;
            float m3 = fmaxf(y3, 0.f) + 1e-7f;
            float4 qq = make_float4(expf(m0 * t), expf(m1 * t), expf(m2 * t), expf(m3 * t));
            float4 pp = make_float4(m0 * qq.x, m1 * qq.y, m2 * qq.z, m3 * qq.w);
            *(float4*)&rb[(size_t)r * HID + c0] = rr;
            *(uint4*)&pqb[(size_t)r * HID + c0] = packPQ(pp, qq);
            float r2 = rr.x * rr.x + rr.y * rr.y + rr.z * rr.z + rr.w * rr.w;
            r2 = warpSum(r2);
            if (lane == 0) rnb[r] = sqrtf(r2);
        }
    }
}

// ---------------- final LN + leaky + pooled accumulation ----------------
__global__ __launch_bounds__(128) void final_kernel(
    const float* __restrict__ fn_g, const float* __restrict__ fn_b,
    const int* __restrict__ batch)
{
    __shared__ float s[8];
    int n = blockIdx.x, f = threadIdx.x;
    float x = g_h[n * HID + f];
    float mu = blockSum(x, s) * (1.f / HID);
    float d = x - mu;
    float var = blockSum(d * d, s) * (1.f / HID);
    float y = d * rsqrtf(var + 1e-5f) * fn_g[f] + fn_b[f];
    float v = (y > 0.f) ? y : 0.01f * y;
    int g = batch[n];
    atomicAdd(&g_gsum[g * HID + f], v);
    if (f == 0) atomicAdd(&g_cnt[g], 1.0f);
}
__global__ void pool_div_kernel(float* __restrict__ out) {
    int i = blockIdx.x * blockDim.x + threadIdx.x;
    if (i < N_GRAPH * HID) {
        int g = i >> 7;
        out[i] = g_gsum[i] / fmaxf(g_cnt[g], 1.0f);
    }
}

// ---------------- host launch ----------------
extern "C" void kernel_launch(void* const* d_in, const int* in_sizes, int n_in,
                              void* d_out, int out_size)
{
    const float* x     = (const float*)d_in[0];
    const int*   ei    = (const int*)d_in[1];
    const int*   batch = (const int*)d_in[2];
    const float* enc_W = (const float*)d_in[3];
    const float* enc_b = (const float*)d_in[4];
    const float* ln_g  = (const float*)d_in[5];
    const float* ln_b  = (const float*)d_in[6];
    const float* t     = (const float*)d_in[7];
    const float* sc    = (const float*)d_in[8];
    const float* W1    = (const float*)d_in[9];
    const float* b1    = (const float*)d_in[10];
    const float* mg    = (const float*)d_in[11];
    const float* mb    = (const float*)d_in[12];
    const float* W2    = (const float*)d_in[13];
    const float* b2    = (const float*)d_in[14];
    const float* fn_g  = (const float*)d_in[15];
    const float* fn_b  = (const float*)d_in[16];
    float* out = (float*)d_out;

    float *p_h, *p_r, *p_rn;
    __half2* p_pq;
    cudaGetSymbolAddress((void**)&p_h,  g_h);
    cudaGetSymbolAddress((void**)&p_r,  g_r);
    cudaGetSymbolAddress((void**)&p_pq, g_PQ);
    cudaGetSymbolAddress((void**)&p_rn, g_rnorm);

    cudaFuncSetAttribute(fused_layer_kernel,
                         cudaFuncAttributeMaxDynamicSharedMemorySize, FUSED_SMEM);

    const int MB  = (N_NODES + 63) / 64;
    const int MBF = (N_NODES + BM - 1) / BM;  // 139 blocks, one wave

    // CSR build + pool zero
    zero_kernel<<<(N_NODES + 255) / 256, 256>>>();
    csr_count_kernel<<<(N_EDGES + 255) / 256, 256>>>(ei);
    scan_kernel<<<1, 1024>>>();
    csr_fill_kernel<<<(N_EDGES + 255) / 256, 256>>>(ei);

    // encoder: h = x @ enc_W + enc_b
    gemm_kernel<<<dim3(1, MB), 256>>>(x, enc_W, enc_b, p_h, N_NODES, HID, HID);
    // pre for layer 0
    node_pre_kernel<<<N_NODES, 128>>>(ln_g, ln_b, t, 0);

    for (int li = 0; li < N_LAYER; li++) {
        fused_layer_kernel<<<MBF, FTHREADS, FUSED_SMEM>>>(
            W1, b1, mg, mb, W2, b2, ln_g, ln_b, t, sc, li,
            (li < N_LAYER - 1) ? 1 : 0, p_h, p_r, p_pq, p_rn);
    }

    final_kernel<<<N_NODES, 128>>>(fn_g, fn_b, batch);
    pool_div_kernel<<<(N_GRAPH * HID + 255) / 256, 256>>>(out);
}

// round 12
// speedup vs baseline: 1.0994x; 1.0994x over previous
#include <cuda_runtime.h>
#include <cuda_bf16.h>
#include <cuda_fp16.h>
#include <math.h>

#define N_NODES 10000
#define N_EDGES 160000
#define N_GRAPH 64
#define HID     128
#define H2      256
#define N_LAYER 14
#define BM      72            // rows per fused-layer block; grid = 139 <= 148 SMs (one wave)
#define FTHREADS 384          // 12 warps, 3 per SMSP

// ---------------- device scratch (no allocations allowed) ----------------
__device__ float   g_h[N_NODES * HID];
__device__ float   g_r[N_NODES * HID];
__device__ float   g_rnorm[N_NODES];
__device__ __half2 g_PQ[N_NODES * HID];   // (P,Q) fp16 pair per feature
__device__ float   g_out[N_NODES * HID];
__device__ int     g_deg[N_NODES];
__device__ int     g_rowptr[N_NODES + 1];
__device__ int     g_cursor[N_NODES];
__device__ int     g_col[N_EDGES];
__device__ float   g_gsum[N_GRAPH * HID];
__device__ float   g_cnt[N_GRAPH];

typedef unsigned long long ull;

// ---------------- helpers ----------------
__device__ __forceinline__ ull pack2(float lo, float hi) {
    ull r;
    asm("mov.b64 %0, {%1,%2};" : "=l"(r) : "f"(lo), "f"(hi));
    return r;
}
__device__ __forceinline__ void unpack2(ull v, float& lo, float& hi) {
    asm("mov.b64 {%0,%1}, %2;" : "=f"(lo), "=f"(hi) : "l"(v));
}
#define FMA_F32X2(d, a, b, c) \
    asm("fma.rn.f32x2 %0, %1, %2, %3;" : "=l"(d) : "l"(a), "l"(b), "l"(c))

__device__ __forceinline__ void cp_async16(float* smem_dst, const float* gmem_src) {
    unsigned sa = (unsigned)__cvta_generic_to_shared(smem_dst);
    asm volatile("cp.async.cg.shared.global [%0], [%1], 16;" :: "r"(sa), "l"(gmem_src));
}
#define CP_COMMIT() asm volatile("cp.async.commit_group;")
#define CP_WAIT0()  asm volatile("cp.async.wait_group 0;")

__device__ __forceinline__ float warpSum(float v) {
    #pragma unroll
    for (int o = 16; o; o >>= 1) v += __shfl_xor_sync(0xffffffffu, v, o);
    return v;
}
__device__ __forceinline__ float blockSum(float v, float* s) {
    #pragma unroll
    for (int o = 16; o; o >>= 1) v += __shfl_down_sync(0xffffffffu, v, o);
    __syncthreads();
    if ((threadIdx.x & 31) == 0) s[threadIdx.x >> 5] = v;
    __syncthreads();
    int nw = blockDim.x >> 5;
    float t = 0.f;
    for (int i = 0; i < nw; i++) t += s[i];
    return t;
}

// pack (p,q) float pairs into half2 lanes of a uint4
__device__ __forceinline__ uint4 packPQ(float4 pp, float4 qq) {
    __half2 h0 = __floats2half2_rn(pp.x, qq.x);
    __half2 h1 = __floats2half2_rn(pp.y, qq.y);
    __half2 h2 = __floats2half2_rn(pp.z, qq.z);
    __half2 h3 = __floats2half2_rn(pp.w, qq.w);
    uint4 u;
    u.x = *(unsigned*)&h0; u.y = *(unsigned*)&h1;
    u.z = *(unsigned*)&h2; u.w = *(unsigned*)&h3;
    return u;
}

// ---------------- zero (CSR counts + pool) ----------------
__global__ void zero_kernel() {
    int i = blockIdx.x * blockDim.x + threadIdx.x;
    if (i < N_NODES) g_deg[i] = 0;
    if (i < N_GRAPH * HID) g_gsum[i] = 0.f;
    if (i < N_GRAPH) g_cnt[i] = 0.f;
}
__global__ void csr_count_kernel(const int* __restrict__ ei) {
    int e = blockIdx.x * blockDim.x + threadIdx.x;
    if (e < N_EDGES) atomicAdd(&g_deg[ei[N_EDGES + e]], 1);
}
__global__ void scan_kernel() {
    __shared__ int s[1024];
    const int CH = 10;
    int t = threadIdx.x;
    int base = t * CH;
    int local[CH];
    int sum = 0;
    #pragma unroll
    for (int j = 0; j < CH; j++) {
        int idx = base + j;
        int v = (idx < N_NODES) ? g_deg[idx] : 0;
        local[j] = sum;
        sum += v;
    }
    s[t] = sum;
    __syncthreads();
    for (int off = 1; off < 1024; off <<= 1) {
        int v = (t >= off) ? s[t - off] : 0;
        __syncthreads();
        s[t] += v;
        __syncthreads();
    }
    int offset = (t > 0) ? s[t - 1] : 0;
    #pragma unroll
    for (int j = 0; j < CH; j++) {
        int idx = base + j;
        if (idx < N_NODES) {
            g_rowptr[idx] = offset + local[j];
            g_cursor[idx] = offset + local[j];
        }
    }
    if (t == 1023) g_rowptr[N_NODES] = s[1023];
}
__global__ void csr_fill_kernel(const int* __restrict__ ei) {
    int e = blockIdx.x * blockDim.x + threadIdx.x;
    if (e < N_EDGES) {
        int d = ei[N_EDGES + e];
        int p = atomicAdd(&g_cursor[d], 1);
        g_col[p] = ei[e];
    }
}

// ---------------- encoder GEMM: h = x @ enc_W + enc_b, fused layer-0 node_pre ------
__global__ __launch_bounds__(256) void gemm_kernel(
    const float* __restrict__ A, const float* __restrict__ B,
    const float* __restrict__ bias, float* __restrict__ Cout,
    int M, int N, int K,
    const float* __restrict__ ln_g, const float* __restrict__ ln_b,
    const float* __restrict__ tptr,
    float* __restrict__ rb, __half2* __restrict__ pqb, float* __restrict__ rnb)
{
    __shared__ float As[16][64];
    __shared__ float Bs[16][128];
    int tid = threadIdx.x;
    int bm = blockIdx.y * 64;
    int bn = blockIdx.x * 128;
    int tr = tid >> 5;
    int tc = tid & 31;
    int lane = tc;
    int row0 = tr * 8, col0 = tc * 4;

    ull acc[8][2];
    #pragma unroll
    for (int i = 0; i < 8; i++) { acc[i][0] = 0ull; acc[i][1] = 0ull; }

    int a_row = tid >> 2;
    int a_col = (tid & 3) * 4;

    for (int k0 = 0; k0 < K; k0 += 16) {
        float4 av = make_float4(0.f, 0.f, 0.f, 0.f);
        int gr = bm + a_row;
        if (gr < M) av = *(const float4*)&A[(size_t)gr * K + k0 + a_col];
        As[a_col + 0][a_row] = av.x;
        As[a_col + 1][a_row] = av.y;
        As[a_col + 2][a_row] = av.z;
        As[a_col + 3][a_row] = av.w;
        #pragma unroll
        for (int i = 0; i < 2; i++) {
            int f = tid + i * 256;
            int br = f >> 5, bc = (f & 31) * 4;
            *(float4*)&Bs[br][bc] = *(const float4*)&B[(size_t)(k0 + br) * N + bn + bc];
        }
        __syncthreads();
        #pragma unroll
        for (int k = 0; k < 16; k++) {
            float a[8];
            *(float4*)&a[0] = *(const float4*)&As[k][row0];
            *(float4*)&a[4] = *(const float4*)&As[k][row0 + 4];
            ulonglong2 bb = *(const ulonglong2*)&Bs[k][col0];
            #pragma unroll
            for (int i = 0; i < 8; i++) {
                ull aa = pack2(a[i], a[i]);
                FMA_F32X2(acc[i][0], aa, bb.x, acc[i][0]);
                FMA_F32X2(acc[i][1], aa, bb.y, acc[i][1]);
            }
        }
        __syncthreads();
    }

    int c = bn + col0;
    float4 bv = *(const float4*)&bias[c];
    float4 gv = *(const float4*)&ln_g[c];
    float4 lb = *(const float4*)&ln_b[c];
    float tval = tptr[0];
    #pragma unroll
    for (int i = 0; i < 8; i++) {
        int r = bm + row0 + i;
        if (r >= M) break;                 // r is warp-uniform: uniform break
        float v0, v1, v2, v3;
        unpack2(acc[i][0], v0, v1);
        unpack2(acc[i][1], v2, v3);
        float4 o = make_float4(v0 + bv.x, v1 + bv.y, v2 + bv.z, v3 + bv.w);
        *(float4*)&Cout[(size_t)r * N + c] = o;
        // ---- fused layer-0 node_pre (warp covers the full 128-wide row) ----
        float s1 = (o.x + o.y) + (o.z + o.w);
        float s2 = o.x * o.x + o.y * o.y + o.z * o.z + o.w * o.w;
        s1 = warpSum(s1);
        s2 = warpSum(s2);
        float mu  = s1 * (1.f / HID);
        float var = s2 * (1.f / HID) - mu * mu;
        float is  = rsqrtf(var + 1e-5f);
        float y0 = (o.x - mu) * is * gv.x + lb.x;
        float y1 = (o.y - mu) * is * gv.y + lb.y;
        float y2 = (o.z - mu) * is * gv.z + lb.z;
        float y3 = (o.w - mu) * is * gv.w + lb.w;
        float4 rr = make_float4((y0 > 0.f) ? y0 : 0.01f * y0,
                                (y1 > 0.f) ? y1 : 0.01f * y1,
                                (y2 > 0.f) ? y2 : 0.01f * y2,
                                (y3 > 0.f) ? y3 : 0.01f * y3);
        float m0 = fmaxf(y0, 0.f) + 1e-7f;
        float m1 = fmaxf(y1, 0.f) + 1e-7f;
        float m2 = fmaxf(y2, 0.f) + 1e-7f;
        float m3 = fmaxf(y3, 0.f) + 1e-7f;
        float4 qq = make_float4(expf(m0 * tval), expf(m1 * tval),
                                expf(m2 * tval), expf(m3 * tval));
        float4 pp = make_float4(m0 * qq.x, m1 * qq.y, m2 * qq.z, m3 * qq.w);
        *(float4*)&rb[(size_t)r * HID + c] = rr;
        *(uint4*)&pqb[(size_t)r * HID + c] = packPQ(pp, qq);
        float r2 = rr.x * rr.x + rr.y * rr.y + rr.z * rr.z + rr.w * rr.w;
        r2 = warpSum(r2);
        if (lane == 0) rnb[r] = sqrtf(r2);
    }
}

// ---------------- aggregation: warp-per-node, fp16 (P,Q) pairs, 4-edge unroll -----
__global__ __launch_bounds__(256) void aggregate_kernel(
    const float* __restrict__ scptr, int li)
{
    int warp = threadIdx.x >> 5, lane = threadIdx.x & 31;
    int n = blockIdx.x * 8 + warp;
    if (n >= N_NODES) return;
    int f = lane * 4;
    int st = g_rowptr[n], en = g_rowptr[n + 1];
    float4 num = make_float4(0.f, 0.f, 0.f, 0.f);
    float4 den = make_float4(0.f, 0.f, 0.f, 0.f);
    int e = st;
    for (; e + 3 < en; e += 4) {
        int s0 = __ldg(&g_col[e]);
        int s1 = __ldg(&g_col[e + 1]);
        int s2 = __ldg(&g_col[e + 2]);
        int s3 = __ldg(&g_col[e + 3]);
        uint4 u0 = *(const uint4*)&g_PQ[s0 * HID + f];
        uint4 u1 = *(const uint4*)&g_PQ[s1 * HID + f];
        uint4 u2 = *(const uint4*)&g_PQ[s2 * HID + f];
        uint4 u3 = *(const uint4*)&g_PQ[s3 * HID + f];
        float2 t;
        t = __half22float2(*(__half2*)&u0.x); num.x += t.x; den.x += t.y;
        t = __half22float2(*(__half2*)&u0.y); num.y += t.x; den.y += t.y;
        t = __half22float2(*(__half2*)&u0.z); num.z += t.x; den.z += t.y;
        t = __half22float2(*(__half2*)&u0.w); num.w += t.x; den.w += t.y;
        t = __half22float2(*(__half2*)&u1.x); num.x += t.x; den.x += t.y;
        t = __half22float2(*(__half2*)&u1.y); num.y += t.x; den.y += t.y;
        t = __half22float2(*(__half2*)&u1.z); num.z += t.x; den.z += t.y;
        t = __half22float2(*(__half2*)&u1.w); num.w += t.x; den.w += t.y;
        t = __half22float2(*(__half2*)&u2.x); num.x += t.x; den.x += t.y;
        t = __half22float2(*(__half2*)&u2.y); num.y += t.x; den.y += t.y;
        t = __half22float2(*(__half2*)&u2.z); num.z += t.x; den.z += t.y;
        t = __half22float2(*(__half2*)&u2.w); num.w += t.x; den.w += t.y;
        t = __half22float2(*(__half2*)&u3.x); num.x += t.x; den.x += t.y;
        t = __half22float2(*(__half2*)&u3.y); num.y += t.x; den.y += t.y;
        t = __half22float2(*(__half2*)&u3.z); num.z += t.x; den.z += t.y;
        t = __half22float2(*(__half2*)&u3.w); num.w += t.x; den.w += t.y;
    }
    for (; e < en; e++) {
        int s0 = __ldg(&g_col[e]);
        uint4 u0 = *(const uint4*)&g_PQ[s0 * HID + f];
        float2 t;
        t = __half22float2(*(__half2*)&u0.x); num.x += t.x; den.x += t.y;
        t = __half22float2(*(__half2*)&u0.y); num.y += t.x; den.y += t.y;
        t = __half22float2(*(__half2*)&u0.z); num.z += t.x; den.z += t.y;
        t = __half22float2(*(__half2*)&u0.w); num.w += t.x; den.w += t.y;
    }
    float4 agg;
    agg.x = num.x / (den.x + 1e-16f);
    agg.y = num.y / (den.y + 1e-16f);
    agg.z = num.z / (den.z + 1e-16f);
    agg.w = num.w / (den.w + 1e-16f);
    float n2 = warpSum(agg.x * agg.x + agg.y * agg.y + agg.z * agg.z + agg.w * agg.w);
    float inv = 1.f / fmaxf(sqrtf(n2), 1e-12f);
    float coef = inv * g_rnorm[n] * scptr[li];
    float4 rv = *(const float4*)&g_r[(size_t)n * HID + f];
    float4 o = make_float4(rv.x + agg.x * coef, rv.y + agg.y * coef,
                           rv.z + agg.z * coef, rv.w + agg.w * coef);
    *(float4*)&g_out[(size_t)n * HID + f] = o;
}

// ---------------- fused layer: GEMM1 + LN+ReLU + GEMM2 + residual + next pre ------
// BM=72, 384 threads (12 warps, 3/SMSP). Warp w owns rows 6w..6w+5. grid 139.
#define Z1_STRIDE 260
#define HS_STRIDE 132
#define ASTRIDE   76
#define AS_OFF    (BM * Z1_STRIDE)               // 18720
#define BS_OFF    (AS_OFF + 2 * 16 * ASTRIDE)    // 21152
#define FUSED_SMEM ((BS_OFF + 2 * 16 * 256) * 4) // 117376 bytes

__global__ void __launch_bounds__(FTHREADS) fused_layer_kernel(
    const float* __restrict__ W1, const float* __restrict__ b1,
    const float* __restrict__ mg, const float* __restrict__ mb,
    const float* __restrict__ W2, const float* __restrict__ b2,
    const float* __restrict__ ln_g, const float* __restrict__ ln_b,
    const float* __restrict__ tptr, int li, int do_pre,
    float* __restrict__ hb, const float* __restrict__ ob,
    float* __restrict__ rb, __half2* __restrict__ pqb,
    float* __restrict__ rnb)
{
    extern __shared__ float sm[];
    float* z1s = sm;                 // [72][260]
    float* As0 = sm + AS_OFF;        // double buffer [2][16][76]
    float* Bs0 = sm + BS_OFF;        // double buffer [2][16][256] (C: [2][16][128])

    const int tid  = threadIdx.x;
    const int warp = tid >> 5, lane = tid & 31;
    const int bm   = blockIdx.x * BM;
    const int row0 = warp * 6;       // 6 rows per warp
    const int c0   = lane * 4;

    // ======== Stage A: z1 = out @ W1 + b1  (72x256, K=128) ========
    ull acc[6][4];
    #pragma unroll
    for (int i = 0; i < 6; i++)
        #pragma unroll
        for (int j = 0; j < 4; j++) acc[i][j] = 0ull;

    const float* Wl1 = W1 + (size_t)li * HID * H2;
    const int ar = tid >> 2;          // 0..95 (only <72 active)
    const int ac = (tid & 3) * 4;     // 0,4,8,12
    const bool aact = (ar < BM);

    {
        #pragma unroll
        for (int i = 0; i < 3; i++) {
            int idx = tid + i * FTHREADS;
            if (idx < 1024) cp_async16(Bs0 + idx * 4, Wl1 + idx * 4);
        }
        CP_COMMIT();
    }
    int garow = bm + ar;
    if (garow >= N_NODES) garow = N_NODES - 1;
    float4 av = make_float4(0.f, 0.f, 0.f, 0.f);
    if (aact) av = *(const float4*)&ob[(size_t)garow * HID + ac];

    int buf = 0;
    for (int k0 = 0; k0 < HID; k0 += 16) {
        float* Asb = As0 + buf * (16 * ASTRIDE);
        float* Bsb = Bs0 + buf * (16 * 256);
        if (aact) {
            Asb[(ac + 0) * ASTRIDE + ar] = av.x;
            Asb[(ac + 1) * ASTRIDE + ar] = av.y;
            Asb[(ac + 2) * ASTRIDE + ar] = av.z;
            Asb[(ac + 3) * ASTRIDE + ar] = av.w;
        }
        CP_WAIT0();
        __syncthreads();
        if (k0 + 16 < HID) {
            if (aact) av = *(const float4*)&ob[(size_t)garow * HID + k0 + 16 + ac];
            float* dst = Bs0 + (buf ^ 1) * (16 * 256);
            const float* srcb = Wl1 + (size_t)(k0 + 16) * H2;
            #pragma unroll
            for (int i = 0; i < 3; i++) {
                int idx = tid + i * FTHREADS;
                if (idx < 1024) cp_async16(dst + idx * 4, srcb + idx * 4);
            }
            CP_COMMIT();
        }
        #pragma unroll
        for (int k = 0; k < 16; k++) {
            const float* Ak = Asb + k * ASTRIDE;
            ull r01 = *(const ull*)&Ak[row0];
            ull r23 = *(const ull*)&Ak[row0 + 2];
            ull r45 = *(const ull*)&Ak[row0 + 4];
            const float* Bk = Bsb + k * 256;
            ulonglong2 bA = *(const ulonglong2*)&Bk[c0];
            ulonglong2 bB = *(const ulonglong2*)&Bk[128 + c0];
            float a[6];
            unpack2(r01, a[0], a[1]);
            unpack2(r23, a[2], a[3]);
            unpack2(r45, a[4], a[5]);
            #pragma unroll
            for (int i = 0; i < 6; i++) {
                ull aa = pack2(a[i], a[i]);
                FMA_F32X2(acc[i][0], aa, bA.x, acc[i][0]);
                FMA_F32X2(acc[i][1], aa, bA.y, acc[i][1]);
                FMA_F32X2(acc[i][2], aa, bB.x, acc[i][2]);
                FMA_F32X2(acc[i][3], aa, bB.y, acc[i][3]);
            }
        }
        buf ^= 1;
    }
    __syncthreads();

    // write z1 tile (+bias) to smem
    {
        float4 bvA = *(const float4*)&b1[(size_t)li * H2 + c0];
        float4 bvB = *(const float4*)&b1[(size_t)li * H2 + 128 + c0];
        #pragma unroll
        for (int i = 0; i < 6; i++) {
            int row = row0 + i;
            float v0, v1, v2, v3;
            unpack2(acc[i][0], v0, v1);
            unpack2(acc[i][1], v2, v3);
            float4 oA = make_float4(v0 + bvA.x, v1 + bvA.y, v2 + bvA.z, v3 + bvA.w);
            unpack2(acc[i][2], v0, v1);
            unpack2(acc[i][3], v2, v3);
            float4 oB = make_float4(v0 + bvB.x, v1 + bvB.y, v2 + bvB.z, v3 + bvB.w);
            *(float4*)&z1s[row * Z1_STRIDE + c0]       = oA;
            *(float4*)&z1s[row * Z1_STRIDE + 128 + c0] = oB;
        }
    }

    // ======== LayerNorm(256) + ReLU in smem (rows are warp-local) ========
    {
        float4 gA = *(const float4*)&mg[(size_t)li * H2 + c0];
        float4 gB = *(const float4*)&mg[(size_t)li * H2 + 128 + c0];
        float4 bA = *(const float4*)&mb[(size_t)li * H2 + c0];
        float4 bB = *(const float4*)&mb[(size_t)li * H2 + 128 + c0];
        #pragma unroll
        for (int i = 0; i < 6; i++) {
            float* rp = &z1s[(row0 + i) * Z1_STRIDE];
            float4 vA = *(const float4*)&rp[c0];
            float4 vB = *(const float4*)&rp[128 + c0];
            float s1 = (vA.x + vA.y) + (vA.z + vA.w) + (vB.x + vB.y) + (vB.z + vB.w);
            float s2 = vA.x * vA.x + vA.y * vA.y + vA.z * vA.z + vA.w * vA.w
                     + vB.x * vB.x + vB.y * vB.y + vB.z * vB.z + vB.w * vB.w;
            s1 = warpSum(s1);
            s2 = warpSum(s2);
            float mu  = s1 * (1.f / H2);
            float var = s2 * (1.f / H2) - mu * mu;
            float is  = rsqrtf(var + 1e-5f);
            vA.x = fmaxf((vA.x - mu) * is * gA.x + bA.x, 0.f);
            vA.y = fmaxf((vA.y - mu) * is * gA.y + bA.y, 0.f);
            vA.z = fmaxf((vA.z - mu) * is * gA.z + bA.z, 0.f);
            vA.w = fmaxf((vA.w - mu) * is * gA.w + bA.w, 0.f);
            vB.x = fmaxf((vB.x - mu) * is * gB.x + bB.x, 0.f);
            vB.y = fmaxf((vB.y - mu) * is * gB.y + bB.y, 0.f);
            vB.z = fmaxf((vB.z - mu) * is * gB.z + bB.z, 0.f);
            vB.w = fmaxf((vB.w - mu) * is * gB.w + bB.w, 0.f);
            *(float4*)&rp[c0]       = vA;
            *(float4*)&rp[128 + c0] = vB;
        }
    }
    __syncthreads();

    // ======== Stage C: h' = h + a @ W2 + b2  (72x128, K=256) ========
    ull acc2[6][2];
    #pragma unroll
    for (int i = 0; i < 6; i++) { acc2[i][0] = 0ull; acc2[i][1] = 0ull; }

    const float* Wl2 = W2 + (size_t)li * H2 * HID;
    {
        #pragma unroll
        for (int i = 0; i < 2; i++) {
            int idx = tid + i * FTHREADS;
            if (idx < 512) cp_async16(Bs0 + idx * 4, Wl2 + idx * 4);
        }
        CP_COMMIT();
    }
    buf = 0;
    for (int k0 = 0; k0 < H2; k0 += 16) {
        CP_WAIT0();
        __syncthreads();
        float* Bsb = Bs0 + buf * (16 * 128);
        if (k0 + 16 < H2) {
            float* dst = Bs0 + (buf ^ 1) * (16 * 128);
            const float* srcb = Wl2 + (size_t)(k0 + 16) * HID;
            #pragma unroll
            for (int i = 0; i < 2; i++) {
                int idx = tid + i * FTHREADS;
                if (idx < 512) cp_async16(dst + idx * 4, srcb + idx * 4);
            }
            CP_COMMIT();
        }
        #pragma unroll
        for (int k4 = 0; k4 < 4; k4++) {
            float4 a4[6];
            #pragma unroll
            for (int i = 0; i < 6; i++)
                a4[i] = *(const float4*)&z1s[(row0 + i) * Z1_STRIDE + k0 + k4 * 4];
            #pragma unroll
            for (int kk = 0; kk < 4; kk++) {
                ulonglong2 bb = *(const ulonglong2*)&Bsb[(k4 * 4 + kk) * 128 + c0];
                #pragma unroll
                for (int i = 0; i < 6; i++) {
                    float avv = (kk == 0) ? a4[i].x : (kk == 1) ? a4[i].y
                              : (kk == 2) ? a4[i].z : a4[i].w;
                    ull aa = pack2(avv, avv);
                    FMA_F32X2(acc2[i][0], aa, bb.x, acc2[i][0]);
                    FMA_F32X2(acc2[i][1], aa, bb.y, acc2[i][1]);
                }
            }
        }
        buf ^= 1;
    }
    __syncthreads();   // all warps done reading z1s before hs aliases it

    // epilogue: residual add, write h, stash tile in smem (reuse z1s region)
    float* hs = sm;  // [72][132]
    {
        float4 bv = *(const float4*)&b2[(size_t)li * HID + c0];
        #pragma unroll
        for (int i = 0; i < 6; i++) {
            int row = row0 + i;
            int r = bm + row;
            float v0, v1, v2, v3;
            unpack2(acc2[i][0], v0, v1);
            unpack2(acc2[i][1], v2, v3);
            float4 o = make_float4(v0 + bv.x, v1 + bv.y, v2 + bv.z, v3 + bv.w);
            if (r < N_NODES) {
                float4 hold = *(const float4*)&hb[(size_t)r * HID + c0];
                o.x += hold.x; o.y += hold.y; o.z += hold.z; o.w += hold.w;
                *(float4*)&hb[(size_t)r * HID + c0] = o;
            }
            *(float4*)&hs[row * HS_STRIDE + c0] = o;
        }
    }

    // ======== next-layer node_pre fused (rows warp-local) ========
    if (do_pre) {
        int ln = li + 1;
        float4 gv = *(const float4*)&ln_g[(size_t)ln * HID + c0];
        float4 bb = *(const float4*)&ln_b[(size_t)ln * HID + c0];
        float t = tptr[ln];
        #pragma unroll
        for (int i = 0; i < 6; i++) {
            int row = row0 + i;
            int r = bm + row;
            if (r >= N_NODES) continue;
            float4 v = *(const float4*)&hs[row * HS_STRIDE + c0];
            float s1 = (v.x + v.y) + (v.z + v.w);
            float s2 = v.x * v.x + v.y * v.y + v.z * v.z + v.w * v.w;
            s1 = warpSum(s1);
            s2 = warpSum(s2);
            float mu  = s1 * (1.f / HID);
            float var = s2 * (1.f / HID) - mu * mu;
            float is  = rsqrtf(var + 1e-5f);
            float y0 = (v.x - mu) * is * gv.x + bb.x;
            float y1 = (v.y - mu) * is * gv.y + bb.y;
            float y2 = (v.z - mu) * is * gv.z + bb.z;
            float y3 = (v.w - mu) * is * gv.w + bb.w;
            float4 rr = make_float4((y0 > 0.f) ? y0 : 0.01f * y0,
                                    (y1 > 0.f) ? y1 : 0.01f * y1,
                                    (y2 > 0.f) ? y2 : 0.01f * y2,
                                    (y3 > 0.f) ? y3 : 0.01f * y3);
            float m0 = fmaxf(y0, 0.f) + 1e-7f;
            float m1 = fmaxf(y1, 0.f) + 1e-7f;
            float m2 = fmaxf(y2, 0.f) + 1e-7f;
            float m3 = fmaxf(y3, 0.f) + 1e-7f;
            float4 qq = make_float4(expf(m0 * t), expf(m1 * t), expf(m2 * t), expf(m3 * t));
            float4 pp = make_float4(m0 * qq.x, m1 * qq.y, m2 * qq.z, m3 * qq.w);
            *(float4*)&rb[(size_t)r * HID + c0] = rr;
            *(uint4*)&pqb[(size_t)r * HID + c0] = packPQ(pp, qq);
            float r2 = rr.x * rr.x + rr.y * rr.y + rr.z * rr.z + rr.w * rr.w;
            r2 = warpSum(r2);
            if (lane == 0) rnb[r] = sqrtf(r2);
        }
    }
}

// ---------------- final LN + leaky + pooled accumulation ----------------
__global__ __launch_bounds__(128) void final_kernel(
    const float* __restrict__ fn_g, const float* __restrict__ fn_b,
    const int* __restrict__ batch)
{
    __shared__ float s[8];
    int n = blockIdx.x, f = threadIdx.x;
    float x = g_h[n * HID + f];
    float mu = blockSum(x, s) * (1.f / HID);
    float d = x - mu;
    float var = blockSum(d * d, s) * (1.f / HID);
    float y = d * rsqrtf(var + 1e-5f) * fn_g[f] + fn_b[f];
    float v = (y > 0.f) ? y : 0.01f * y;
    int g = batch[n];
    atomicAdd(&g_gsum[g * HID + f], v);
    if (f == 0) atomicAdd(&g_cnt[g], 1.0f);
}
__global__ void pool_div_kernel(float* __restrict__ out) {
    int i = blockIdx.x * blockDim.x + threadIdx.x;
    if (i < N_GRAPH * HID) {
        int g = i >> 7;
        out[i] = g_gsum[i] / fmaxf(g_cnt[g], 1.0f);
    }
}

// ---------------- host launch ----------------
extern "C" void kernel_launch(void* const* d_in, const int* in_sizes, int n_in,
                              void* d_out, int out_size)
{
    const float* x     = (const float*)d_in[0];
    const int*   ei    = (const int*)d_in[1];
    const int*   batch = (const int*)d_in[2];
    const float* enc_W = (const float*)d_in[3];
    const float* enc_b = (const float*)d_in[4];
    const float* ln_g  = (const float*)d_in[5];
    const float* ln_b  = (const float*)d_in[6];
    const float* t     = (const float*)d_in[7];
    const float* sc    = (const float*)d_in[8];
    const float* W1    = (const float*)d_in[9];
    const float* b1    = (const float*)d_in[10];
    const float* mg    = (const float*)d_in[11];
    const float* mb    = (const float*)d_in[12];
    const float* W2    = (const float*)d_in[13];
    const float* b2    = (const float*)d_in[14];
    const float* fn_g  = (const float*)d_in[15];
    const float* fn_b  = (const float*)d_in[16];
    float* out = (float*)d_out;

    float *p_h, *p_r, *p_rn, *p_out;
    __half2* p_pq;
    cudaGetSymbolAddress((void**)&p_h,   g_h);
    cudaGetSymbolAddress((void**)&p_r,   g_r);
    cudaGetSymbolAddress((void**)&p_pq,  g_PQ);
    cudaGetSymbolAddress((void**)&p_rn,  g_rnorm);
    cudaGetSymbolAddress((void**)&p_out, g_out);

    cudaFuncSetAttribute(fused_layer_kernel,
                         cudaFuncAttributeMaxDynamicSharedMemorySize, FUSED_SMEM);

    const int MB  = (N_NODES + 63) / 64;
    const int MBF = (N_NODES + BM - 1) / BM;  // 139 blocks, one wave

    // CSR build + pool zero
    zero_kernel<<<(N_NODES + 255) / 256, 256>>>();
    csr_count_kernel<<<(N_EDGES + 255) / 256, 256>>>(ei);
    scan_kernel<<<1, 1024>>>();
    csr_fill_kernel<<<(N_EDGES + 255) / 256, 256>>>(ei);

    // encoder: h = x @ enc_W + enc_b, with fused layer-0 node_pre
    gemm_kernel<<<dim3(1, MB), 256>>>(x, enc_W, enc_b, p_h, N_NODES, HID, HID,
                                      ln_g, ln_b, t, p_r, p_pq, p_rn);

    for (int li = 0; li < N_LAYER; li++) {
        aggregate_kernel<<<(N_NODES + 7) / 8, 256>>>(sc, li);
        fused_layer_kernel<<<MBF, FTHREADS, FUSED_SMEM>>>(
            W1, b1, mg, mb, W2, b2, ln_g, ln_b, t, li, (li < N_LAYER - 1) ? 1 : 0,
            p_h, p_out, p_r, p_pq, p_rn);
    }

    final_kernel<<<N_NODES, 128>>>(fn_g, fn_b, batch);
    pool_div_kernel<<<(N_GRAPH * HID + 255) / 256, 256>>>(out);
}

// round 13
// speedup vs baseline: 1.1381x; 1.0352x over previous
#include <cuda_runtime.h>
#include <cuda_bf16.h>
#include <cuda_fp16.h>
#include <math.h>

#define N_NODES 10000
#define N_EDGES 160000
#define N_GRAPH 64
#define HID     128
#define H2      256
#define N_LAYER 14
#define BM      72            // rows per fused-layer block; grid = 139 <= 148 SMs (one wave)
#define FTHREADS 384          // 12 warps, 3 per SMSP
#define BK      32            // k-tile for both fused GEMM stages

// ---------------- device scratch (no allocations allowed) ----------------
__device__ float   g_h[N_NODES * HID];
__device__ float   g_r[N_NODES * HID];
__device__ float   g_rnorm[N_NODES];
__device__ __half2 g_PQ[N_NODES * HID];   // (P,Q) fp16 pair per feature
__device__ float   g_out[N_NODES * HID];
__device__ int     g_deg[N_NODES];
__device__ int     g_rowptr[N_NODES + 1];
__device__ int     g_cursor[N_NODES];
__device__ int     g_col[N_EDGES];
__device__ float   g_gsum[N_GRAPH * HID];
__device__ float   g_cnt[N_GRAPH];

typedef unsigned long long ull;

// ---------------- helpers ----------------
__device__ __forceinline__ ull pack2(float lo, float hi) {
    ull r;
    asm("mov.b64 %0, {%1,%2};" : "=l"(r) : "f"(lo), "f"(hi));
    return r;
}
__device__ __forceinline__ void unpack2(ull v, float& lo, float& hi) {
    asm("mov.b64 {%0,%1}, %2;" : "=f"(lo), "=f"(hi) : "l"(v));
}
#define FMA_F32X2(d, a, b, c) \
    asm("fma.rn.f32x2 %0, %1, %2, %3;" : "=l"(d) : "l"(a), "l"(b), "l"(c))

__device__ __forceinline__ void cp_async16(float* smem_dst, const float* gmem_src) {
    unsigned sa = (unsigned)__cvta_generic_to_shared(smem_dst);
    asm volatile("cp.async.cg.shared.global [%0], [%1], 16;" :: "r"(sa), "l"(gmem_src));
}
#define CP_COMMIT() asm volatile("cp.async.commit_group;")
#define CP_WAIT0()  asm volatile("cp.async.wait_group 0;")

__device__ __forceinline__ float warpSum(float v) {
    #pragma unroll
    for (int o = 16; o; o >>= 1) v += __shfl_xor_sync(0xffffffffu, v, o);
    return v;
}
__device__ __forceinline__ float blockSum(float v, float* s) {
    #pragma unroll
    for (int o = 16; o; o >>= 1) v += __shfl_down_sync(0xffffffffu, v, o);
    __syncthreads();
    if ((threadIdx.x & 31) == 0) s[threadIdx.x >> 5] = v;
    __syncthreads();
    int nw = blockDim.x >> 5;
    float t = 0.f;
    for (int i = 0; i < nw; i++) t += s[i];
    return t;
}

// pack (p,q) float pairs into half2 lanes of a uint4
__device__ __forceinline__ uint4 packPQ(float4 pp, float4 qq) {
    __half2 h0 = __floats2half2_rn(pp.x, qq.x);
    __half2 h1 = __floats2half2_rn(pp.y, qq.y);
    __half2 h2 = __floats2half2_rn(pp.z, qq.z);
    __half2 h3 = __floats2half2_rn(pp.w, qq.w);
    uint4 u;
    u.x = *(unsigned*)&h0; u.y = *(unsigned*)&h1;
    u.z = *(unsigned*)&h2; u.w = *(unsigned*)&h3;
    return u;
}

// ---------------- zero (CSR counts + pool) ----------------
__global__ void zero_kernel() {
    int i = blockIdx.x * blockDim.x + threadIdx.x;
    if (i < N_NODES) g_deg[i] = 0;
    if (i < N_GRAPH * HID) g_gsum[i] = 0.f;
    if (i < N_GRAPH) g_cnt[i] = 0.f;
}
__global__ void csr_count_kernel(const int* __restrict__ ei) {
    int e = blockIdx.x * blockDim.x + threadIdx.x;
    if (e < N_EDGES) atomicAdd(&g_deg[ei[N_EDGES + e]], 1);
}
__global__ void scan_kernel() {
    __shared__ int s[1024];
    const int CH = 10;
    int t = threadIdx.x;
    int base = t * CH;
    int local[CH];
    int sum = 0;
    #pragma unroll
    for (int j = 0; j < CH; j++) {
        int idx = base + j;
        int v = (idx < N_NODES) ? g_deg[idx] : 0;
        local[j] = sum;
        sum += v;
    }
    s[t] = sum;
    __syncthreads();
    for (int off = 1; off < 1024; off <<= 1) {
        int v = (t >= off) ? s[t - off] : 0;
        __syncthreads();
        s[t] += v;
        __syncthreads();
    }
    int offset = (t > 0) ? s[t - 1] : 0;
    #pragma unroll
    for (int j = 0; j < CH; j++) {
        int idx = base + j;
        if (idx < N_NODES) {
            g_rowptr[idx] = offset + local[j];
            g_cursor[idx] = offset + local[j];
        }
    }
    if (t == 1023) g_rowptr[N_NODES] = s[1023];
}
__global__ void csr_fill_kernel(const int* __restrict__ ei) {
    int e = blockIdx.x * blockDim.x + threadIdx.x;
    if (e < N_EDGES) {
        int d = ei[N_EDGES + e];
        int p = atomicAdd(&g_cursor[d], 1);
        g_col[p] = ei[e];
    }
}

// ---------------- encoder GEMM: h = x @ enc_W + enc_b, fused layer-0 node_pre ------
__global__ __launch_bounds__(256) void gemm_kernel(
    const float* __restrict__ A, const float* __restrict__ B,
    const float* __restrict__ bias, float* __restrict__ Cout,
    int M, int N, int K,
    const float* __restrict__ ln_g, const float* __restrict__ ln_b,
    const float* __restrict__ tptr,
    float* __restrict__ rb, __half2* __restrict__ pqb, float* __restrict__ rnb)
{
    __shared__ float As[16][64];
    __shared__ float Bs[16][128];
    int tid = threadIdx.x;
    int bm = blockIdx.y * 64;
    int bn = blockIdx.x * 128;
    int tr = tid >> 5;
    int tc = tid & 31;
    int lane = tc;
    int row0 = tr * 8, col0 = tc * 4;

    ull acc[8][2];
    #pragma unroll
    for (int i = 0; i < 8; i++) { acc[i][0] = 0ull; acc[i][1] = 0ull; }

    int a_row = tid >> 2;
    int a_col = (tid & 3) * 4;

    for (int k0 = 0; k0 < K; k0 += 16) {
        float4 av = make_float4(0.f, 0.f, 0.f, 0.f);
        int gr = bm + a_row;
        if (gr < M) av = *(const float4*)&A[(size_t)gr * K + k0 + a_col];
        As[a_col + 0][a_row] = av.x;
        As[a_col + 1][a_row] = av.y;
        As[a_col + 2][a_row] = av.z;
        As[a_col + 3][a_row] = av.w;
        #pragma unroll
        for (int i = 0; i < 2; i++) {
            int f = tid + i * 256;
            int br = f >> 5, bc = (f & 31) * 4;
            *(float4*)&Bs[br][bc] = *(const float4*)&B[(size_t)(k0 + br) * N + bn + bc];
        }
        __syncthreads();
        #pragma unroll
        for (int k = 0; k < 16; k++) {
            float a[8];
            *(float4*)&a[0] = *(const float4*)&As[k][row0];
            *(float4*)&a[4] = *(const float4*)&As[k][row0 + 4];
            ulonglong2 bb = *(const ulonglong2*)&Bs[k][col0];
            #pragma unroll
            for (int i = 0; i < 8; i++) {
                ull aa = pack2(a[i], a[i]);
                FMA_F32X2(acc[i][0], aa, bb.x, acc[i][0]);
                FMA_F32X2(acc[i][1], aa, bb.y, acc[i][1]);
            }
        }
        __syncthreads();
    }

    int c = bn + col0;
    float4 bv = *(const float4*)&bias[c];
    float4 gv = *(const float4*)&ln_g[c];
    float4 lb = *(const float4*)&ln_b[c];
    float tval = tptr[0];
    #pragma unroll
    for (int i = 0; i < 8; i++) {
        int r = bm + row0 + i;
        if (r >= M) break;                 // r is warp-uniform: uniform break
        float v0, v1, v2, v3;
        unpack2(acc[i][0], v0, v1);
        unpack2(acc[i][1], v2, v3);
        float4 o = make_float4(v0 + bv.x, v1 + bv.y, v2 + bv.z, v3 + bv.w);
        *(float4*)&Cout[(size_t)r * N + c] = o;
        // ---- fused layer-0 node_pre (warp covers the full 128-wide row) ----
        float s1 = (o.x + o.y) + (o.z + o.w);
        float s2 = o.x * o.x + o.y * o.y + o.z * o.z + o.w * o.w;
        s1 = warpSum(s1);
        s2 = warpSum(s2);
        float mu  = s1 * (1.f / HID);
        float var = s2 * (1.f / HID) - mu * mu;
        float is  = rsqrtf(var + 1e-5f);
        float y0 = (o.x - mu) * is * gv.x + lb.x;
        float y1 = (o.y - mu) * is * gv.y + lb.y;
        float y2 = (o.z - mu) * is * gv.z + lb.z;
        float y3 = (o.w - mu) * is * gv.w + lb.w;
        float4 rr = make_float4((y0 > 0.f) ? y0 : 0.01f * y0,
                                (y1 > 0.f) ? y1 : 0.01f * y1,
                                (y2 > 0.f) ? y2 : 0.01f * y2,
                                (y3 > 0.f) ? y3 : 0.01f * y3);
        float m0 = fmaxf(y0, 0.f) + 1e-7f;
        float m1 = fmaxf(y1, 0.f) + 1e-7f;
        float m2 = fmaxf(y2, 0.f) + 1e-7f;
        float m3 = fmaxf(y3, 0.f) + 1e-7f;
        float4 qq = make_float4(expf(m0 * tval), expf(m1 * tval),
                                expf(m2 * tval), expf(m3 * tval));
        float4 pp = make_float4(m0 * qq.x, m1 * qq.y, m2 * qq.z, m3 * qq.w);
        *(float4*)&rb[(size_t)r * HID + c] = rr;
        *(uint4*)&pqb[(size_t)r * HID + c] = packPQ(pp, qq);
        float r2 = rr.x * rr.x + rr.y * rr.y + rr.z * rr.z + rr.w * rr.w;
        r2 = warpSum(r2);
        if (lane == 0) rnb[r] = sqrtf(r2);
    }
}

// ---------------- aggregation: warp-per-node, fp16 (P,Q) pairs, 4-edge unroll -----
__global__ __launch_bounds__(256) void aggregate_kernel(
    const float* __restrict__ scptr, int li)
{
    int warp = threadIdx.x >> 5, lane = threadIdx.x & 31;
    int n = blockIdx.x * 8 + warp;
    if (n >= N_NODES) return;
    int f = lane * 4;
    int st = g_rowptr[n], en = g_rowptr[n + 1];
    float4 num = make_float4(0.f, 0.f, 0.f, 0.f);
    float4 den = make_float4(0.f, 0.f, 0.f, 0.f);
    int e = st;
    for (; e + 3 < en; e += 4) {
        int s0 = __ldg(&g_col[e]);
        int s1 = __ldg(&g_col[e + 1]);
        int s2 = __ldg(&g_col[e + 2]);
        int s3 = __ldg(&g_col[e + 3]);
        uint4 u0 = *(const uint4*)&g_PQ[s0 * HID + f];
        uint4 u1 = *(const uint4*)&g_PQ[s1 * HID + f];
        uint4 u2 = *(const uint4*)&g_PQ[s2 * HID + f];
        uint4 u3 = *(const uint4*)&g_PQ[s3 * HID + f];
        float2 t;
        t = __half22float2(*(__half2*)&u0.x); num.x += t.x; den.x += t.y;
        t = __half22float2(*(__half2*)&u0.y); num.y += t.x; den.y += t.y;
        t = __half22float2(*(__half2*)&u0.z); num.z += t.x; den.z += t.y;
        t = __half22float2(*(__half2*)&u0.w); num.w += t.x; den.w += t.y;
        t = __half22float2(*(__half2*)&u1.x); num.x += t.x; den.x += t.y;
        t = __half22float2(*(__half2*)&u1.y); num.y += t.x; den.y += t.y;
        t = __half22float2(*(__half2*)&u1.z); num.z += t.x; den.z += t.y;
        t = __half22float2(*(__half2*)&u1.w); num.w += t.x; den.w += t.y;
        t = __half22float2(*(__half2*)&u2.x); num.x += t.x; den.x += t.y;
        t = __half22float2(*(__half2*)&u2.y); num.y += t.x; den.y += t.y;
        t = __half22float2(*(__half2*)&u2.z); num.z += t.x; den.z += t.y;
        t = __half22float2(*(__half2*)&u2.w); num.w += t.x; den.w += t.y;
        t = __half22float2(*(__half2*)&u3.x); num.x += t.x; den.x += t.y;
        t = __half22float2(*(__half2*)&u3.y); num.y += t.x; den.y += t.y;
        t = __half22float2(*(__half2*)&u3.z); num.z += t.x; den.z += t.y;
        t = __half22float2(*(__half2*)&u3.w); num.w += t.x; den.w += t.y;
    }
    for (; e < en; e++) {
        int s0 = __ldg(&g_col[e]);
        uint4 u0 = *(const uint4*)&g_PQ[s0 * HID + f];
        float2 t;
        t = __half22float2(*(__half2*)&u0.x); num.x += t.x; den.x += t.y;
        t = __half22float2(*(__half2*)&u0.y); num.y += t.x; den.y += t.y;
        t = __half22float2(*(__half2*)&u0.z); num.z += t.x; den.z += t.y;
        t = __half22float2(*(__half2*)&u0.w); num.w += t.x; den.w += t.y;
    }
    float4 agg;
    agg.x = num.x / (den.x + 1e-16f);
    agg.y = num.y / (den.y + 1e-16f);
    agg.z = num.z / (den.z + 1e-16f);
    agg.w = num.w / (den.w + 1e-16f);
    float n2 = warpSum(agg.x * agg.x + agg.y * agg.y + agg.z * agg.z + agg.w * agg.w);
    float inv = 1.f / fmaxf(sqrtf(n2), 1e-12f);
    float coef = inv * g_rnorm[n] * scptr[li];
    float4 rv = *(const float4*)&g_r[(size_t)n * HID + f];
    float4 o = make_float4(rv.x + agg.x * coef, rv.y + agg.y * coef,
                           rv.z + agg.z * coef, rv.w + agg.w * coef);
    *(float4*)&g_out[(size_t)n * HID + f] = o;
}

// ---------------- fused layer: GEMM1 + LN+ReLU + GEMM2 + residual + next pre ------
// BM=72, 384 threads (12 warps, 3/SMSP), BK=32. Warp w owns rows 6w..6w+5. grid 139.
// smem (floats): z1s[72*260] | As[2][32*76] | Bs[2][32*256]
#define Z1_STRIDE 260
#define HS_STRIDE 132
#define ASTRIDE   76
#define AS_OFF    (BM * Z1_STRIDE)               // 18720
#define BS_OFF    (AS_OFF + 2 * BK * ASTRIDE)    // 18720 + 4864 = 23584
#define FUSED_SMEM ((BS_OFF + 2 * BK * 256) * 4) // (23584 + 16384)*4 = 159872 bytes

__global__ void __launch_bounds__(FTHREADS) fused_layer_kernel(
    const float* __restrict__ W1, const float* __restrict__ b1,
    const float* __restrict__ mg, const float* __restrict__ mb,
    const float* __restrict__ W2, const float* __restrict__ b2,
    const float* __restrict__ ln_g, const float* __restrict__ ln_b,
    const float* __restrict__ tptr, int li, int do_pre,
    float* __restrict__ hb, const float* __restrict__ ob,
    float* __restrict__ rb, __half2* __restrict__ pqb,
    float* __restrict__ rnb)
{
    extern __shared__ float sm[];
    float* z1s = sm;                 // [72][260]
    float* As0 = sm + AS_OFF;        // double buffer [2][32][76]
    float* Bs0 = sm + BS_OFF;        // double buffer [2][32][256] (C: [2][32][128])

    const int tid  = threadIdx.x;
    const int warp = tid >> 5, lane = tid & 31;
    const int bm   = blockIdx.x * BM;
    const int row0 = warp * 6;       // 6 rows per warp
    const int c0   = lane * 4;

    // ======== Stage A: z1 = out @ W1 + b1  (72x256, K=128, BK=32) ========
    ull acc[6][4];
    #pragma unroll
    for (int i = 0; i < 6; i++)
        #pragma unroll
        for (int j = 0; j < 4; j++) acc[i][j] = 0ull;

    const float* Wl1 = W1 + (size_t)li * HID * H2;
    const int ar = tid >> 2;          // 0..95 (only <72 active)
    const int ac = (tid & 3) * 4;     // 0,4,8,12 (plus +16 for second half)
    const bool aact = (ar < BM);

    // prologue: async-stage B(k0=0) = 32x256 floats = 2048 float4
    {
        #pragma unroll
        for (int i = 0; i < 6; i++) {
            int idx = tid + i * FTHREADS;
            if (idx < 2048) cp_async16(Bs0 + idx * 4, Wl1 + idx * 4);
        }
        CP_COMMIT();
    }
    int garow = bm + ar;
    if (garow >= N_NODES) garow = N_NODES - 1;
    float4 av0 = make_float4(0.f, 0.f, 0.f, 0.f);
    float4 av1 = make_float4(0.f, 0.f, 0.f, 0.f);
    if (aact) {
        av0 = *(const float4*)&ob[(size_t)garow * HID + ac];
        av1 = *(const float4*)&ob[(size_t)garow * HID + ac + 16];
    }

    int buf = 0;
    for (int k0 = 0; k0 < HID; k0 += BK) {
        float* Asb = As0 + buf * (BK * ASTRIDE);
        float* Bsb = Bs0 + buf * (BK * 256);
        if (aact) {
            Asb[(ac + 0) * ASTRIDE + ar] = av0.x;
            Asb[(ac + 1) * ASTRIDE + ar] = av0.y;
            Asb[(ac + 2) * ASTRIDE + ar] = av0.z;
            Asb[(ac + 3) * ASTRIDE + ar] = av0.w;
            Asb[(ac + 16) * ASTRIDE + ar] = av1.x;
            Asb[(ac + 17) * ASTRIDE + ar] = av1.y;
            Asb[(ac + 18) * ASTRIDE + ar] = av1.z;
            Asb[(ac + 19) * ASTRIDE + ar] = av1.w;
        }
        CP_WAIT0();
        __syncthreads();
        if (k0 + BK < HID) {
            if (aact) {
                av0 = *(const float4*)&ob[(size_t)garow * HID + k0 + BK + ac];
                av1 = *(const float4*)&ob[(size_t)garow * HID + k0 + BK + ac + 16];
            }
            float* dst = Bs0 + (buf ^ 1) * (BK * 256);
            const float* srcb = Wl1 + (size_t)(k0 + BK) * H2;
            #pragma unroll
            for (int i = 0; i < 6; i++) {
                int idx = tid + i * FTHREADS;
                if (idx < 2048) cp_async16(dst + idx * 4, srcb + idx * 4);
            }
            CP_COMMIT();
        }
        #pragma unroll
        for (int k = 0; k < BK; k++) {
            const float* Ak = Asb + k * ASTRIDE;
            ull r01 = *(const ull*)&Ak[row0];
            ull r23 = *(const ull*)&Ak[row0 + 2];
            ull r45 = *(const ull*)&Ak[row0 + 4];
            const float* Bk = Bsb + k * 256;
            ulonglong2 bA = *(const ulonglong2*)&Bk[c0];
            ulonglong2 bB = *(const ulonglong2*)&Bk[128 + c0];
            float a[6];
            unpack2(r01, a[0], a[1]);
            unpack2(r23, a[2], a[3]);
            unpack2(r45, a[4], a[5]);
            #pragma unroll
            for (int i = 0; i < 6; i++) {
                ull aa = pack2(a[i], a[i]);
                FMA_F32X2(acc[i][0], aa, bA.x, acc[i][0]);
                FMA_F32X2(acc[i][1], aa, bA.y, acc[i][1]);
                FMA_F32X2(acc[i][2], aa, bB.x, acc[i][2]);
                FMA_F32X2(acc[i][3], aa, bB.y, acc[i][3]);
            }
        }
        buf ^= 1;
    }
    __syncthreads();

    // write z1 tile (+bias) to smem
    {
        float4 bvA = *(const float4*)&b1[(size_t)li * H2 + c0];
        float4 bvB = *(const float4*)&b1[(size_t)li * H2 + 128 + c0];
        #pragma unroll
        for (int i = 0; i < 6; i++) {
            int row = row0 + i;
            float v0, v1, v2, v3;
            unpack2(acc[i][0], v0, v1);
            unpack2(acc[i][1], v2, v3);
            float4 oA = make_float4(v0 + bvA.x, v1 + bvA.y, v2 + bvA.z, v3 + bvA.w);
            unpack2(acc[i][2], v0, v1);
            unpack2(acc[i][3], v2, v3);
            float4 oB = make_float4(v0 + bvB.x, v1 + bvB.y, v2 + bvB.z, v3 + bvB.w);
            *(float4*)&z1s[row * Z1_STRIDE + c0]       = oA;
            *(float4*)&z1s[row * Z1_STRIDE + 128 + c0] = oB;
        }
    }

    // ======== LayerNorm(256) + ReLU in smem (rows are warp-local) ========
    {
        float4 gA = *(const float4*)&mg[(size_t)li * H2 + c0];
        float4 gB = *(const float4*)&mg[(size_t)li * H2 + 128 + c0];
        float4 bA = *(const float4*)&mb[(size_t)li * H2 + c0];
        float4 bB = *(const float4*)&mb[(size_t)li * H2 + 128 + c0];
        #pragma unroll
        for (int i = 0; i < 6; i++) {
            float* rp = &z1s[(row0 + i) * Z1_STRIDE];
            float4 vA = *(const float4*)&rp[c0];
            float4 vB = *(const float4*)&rp[128 + c0];
            float s1 = (vA.x + vA.y) + (vA.z + vA.w) + (vB.x + vB.y) + (vB.z + vB.w);
            float s2 = vA.x * vA.x + vA.y * vA.y + vA.z * vA.z + vA.w * vA.w
                     + vB.x * vB.x + vB.y * vB.y + vB.z * vB.z + vB.w * vB.w;
            s1 = warpSum(s1);
            s2 = warpSum(s2);
            float mu  = s1 * (1.f / H2);
            float var = s2 * (1.f / H2) - mu * mu;
            float is  = rsqrtf(var + 1e-5f);
            vA.x = fmaxf((vA.x - mu) * is * gA.x + bA.x, 0.f);
            vA.y = fmaxf((vA.y - mu) * is * gA.y + bA.y, 0.f);
            vA.z = fmaxf((vA.z - mu) * is * gA.z + bA.z, 0.f);
            vA.w = fmaxf((vA.w - mu) * is * gA.w + bA.w, 0.f);
            vB.x = fmaxf((vB.x - mu) * is * gB.x + bB.x, 0.f);
            vB.y = fmaxf((vB.y - mu) * is * gB.y + bB.y, 0.f);
            vB.z = fmaxf((vB.z - mu) * is * gB.z + bB.z, 0.f);
            vB.w = fmaxf((vB.w - mu) * is * gB.w + bB.w, 0.f);
            *(float4*)&rp[c0]       = vA;
            *(float4*)&rp[128 + c0] = vB;
        }
    }
    __syncthreads();

    // ======== Stage C: h' = h + a @ W2 + b2  (72x128, K=256, BK=32) ========
    ull acc2[6][2];
    #pragma unroll
    for (int i = 0; i < 6; i++) { acc2[i][0] = 0ull; acc2[i][1] = 0ull; }

    const float* Wl2 = W2 + (size_t)li * H2 * HID;
    // prologue: async-stage B(k0=0) = 32x128 floats = 1024 float4
    {
        #pragma unroll
        for (int i = 0; i < 3; i++) {
            int idx = tid + i * FTHREADS;
            if (idx < 1024) cp_async16(Bs0 + idx * 4, Wl2 + idx * 4);
        }
        CP_COMMIT();
    }
    buf = 0;
    for (int k0 = 0; k0 < H2; k0 += BK) {
        CP_WAIT0();
        __syncthreads();
        float* Bsb = Bs0 + buf * (BK * 128);
        if (k0 + BK < H2) {
            float* dst = Bs0 + (buf ^ 1) * (BK * 128);
            const float* srcb = Wl2 + (size_t)(k0 + BK) * HID;
            #pragma unroll
            for (int i = 0; i < 3; i++) {
                int idx = tid + i * FTHREADS;
                if (idx < 1024) cp_async16(dst + idx * 4, srcb + idx * 4);
            }
            CP_COMMIT();
        }
        #pragma unroll
        for (int k4 = 0; k4 < BK / 4; k4++) {
            float4 a4[6];
            #pragma unroll
            for (int i = 0; i < 6; i++)
                a4[i] = *(const float4*)&z1s[(row0 + i) * Z1_STRIDE + k0 + k4 * 4];
            #pragma unroll
            for (int kk = 0; kk < 4; kk++) {
                ulonglong2 bb = *(const ulonglong2*)&Bsb[(k4 * 4 + kk) * 128 + c0];
                #pragma unroll
                for (int i = 0; i < 6; i++) {
                    float avv = (kk == 0) ? a4[i].x : (kk == 1) ? a4[i].y
                              : (kk == 2) ? a4[i].z : a4[i].w;
                    ull aa = pack2(avv, avv);
                    FMA_F32X2(acc2[i][0], aa, bb.x, acc2[i][0]);
                    FMA_F32X2(acc2[i][1], aa, bb.y, acc2[i][1]);
                }
            }
        }
        buf ^= 1;
    }
    __syncthreads();   // all warps done reading z1s before hs aliases it

    // epilogue: residual add, write h, stash tile in smem (reuse z1s region)
    float* hs = sm;  // [72][132]
    {
        float4 bv = *(const float4*)&b2[(size_t)li * HID + c0];
        #pragma unroll
        for (int i = 0; i < 6; i++) {
            int row = row0 + i;
            int r = bm + row;
            float v0, v1, v2, v3;
            unpack2(acc2[i][0], v0, v1);
            unpack2(acc2[i][1], v2, v3);
            float4 o = make_float4(v0 + bv.x, v1 + bv.y, v2 + bv.z, v3 + bv.w);
            if (r < N_NODES) {
                float4 hold = *(const float4*)&hb[(size_t)r * HID + c0];
                o.x += hold.x; o.y += hold.y; o.z += hold.z; o.w += hold.w;
                *(float4*)&hb[(size_t)r * HID + c0] = o;
            }
            *(float4*)&hs[row * HS_STRIDE + c0] = o;
        }
    }

    // ======== next-layer node_pre fused (rows warp-local) ========
    if (do_pre) {
        int ln = li + 1;
        float4 gv = *(const float4*)&ln_g[(size_t)ln * HID + c0];
        float4 bb = *(const float4*)&ln_b[(size_t)ln * HID + c0];
        float t = tptr[ln];
        #pragma unroll
        for (int i = 0; i < 6; i++) {
            int row = row0 + i;
            int r = bm + row;
            if (r >= N_NODES) continue;
            float4 v = *(const float4*)&hs[row * HS_STRIDE + c0];
            float s1 = (v.x + v.y) + (v.z + v.w);
            float s2 = v.x * v.x + v.y * v.y + v.z * v.z + v.w * v.w;
            s1 = warpSum(s1);
            s2 = warpSum(s2);
            float mu  = s1 * (1.f / HID);
            float var = s2 * (1.f / HID) - mu * mu;
            float is  = rsqrtf(var + 1e-5f);
            float y0 = (v.x - mu) * is * gv.x + bb.x;
            float y1 = (v.y - mu) * is * gv.y + bb.y;
            float y2 = (v.z - mu) * is * gv.z + bb.z;
            float y3 = (v.w - mu) * is * gv.w + bb.w;
            float4 rr = make_float4((y0 > 0.f) ? y0 : 0.01f * y0,
                                    (y1 > 0.f) ? y1 : 0.01f * y1,
                                    (y2 > 0.f) ? y2 : 0.01f * y2,
                                    (y3 > 0.f) ? y3 : 0.01f * y3);
            float m0 = fmaxf(y0, 0.f) + 1e-7f;
            float m1 = fmaxf(y1, 0.f) + 1e-7f;
            float m2 = fmaxf(y2, 0.f) + 1e-7f;
            float m3 = fmaxf(y3, 0.f) + 1e-7f;
            float4 qq = make_float4(expf(m0 * t), expf(m1 * t), expf(m2 * t), expf(m3 * t));
            float4 pp = make_float4(m0 * qq.x, m1 * qq.y, m2 * qq.z, m3 * qq.w);
            *(float4*)&rb[(size_t)r * HID + c0] = rr;
            *(uint4*)&pqb[(size_t)r * HID + c0] = packPQ(pp, qq);
            float r2 = rr.x * rr.x + rr.y * rr.y + rr.z * rr.z + rr.w * rr.w;
            r2 = warpSum(r2);
            if (lane == 0) rnb[r] = sqrtf(r2);
        }
    }
}

// ---------------- final LN + leaky + pooled accumulation ----------------
__global__ __launch_bounds__(128) void final_kernel(
    const float* __restrict__ fn_g, const float* __restrict__ fn_b,
    const int* __restrict__ batch)
{
    __shared__ float s[8];
    int n = blockIdx.x, f = threadIdx.x;
    float x = g_h[n * HID + f];
    float mu = blockSum(x, s) * (1.f / HID);
    float d = x - mu;
    float var = blockSum(d * d, s) * (1.f / HID);
    float y = d * rsqrtf(var + 1e-5f) * fn_g[f] + fn_b[f];
    float v = (y > 0.f) ? y : 0.01f * y;
    int g = batch[n];
    atomicAdd(&g_gsum[g * HID + f], v);
    if (f == 0) atomicAdd(&g_cnt[g], 1.0f);
}
__global__ void pool_div_kernel(float* __restrict__ out) {
    int i = blockIdx.x * blockDim.x + threadIdx.x;
    if (i < N_GRAPH * HID) {
        int g = i >> 7;
        out[i] = g_gsum[i] / fmaxf(g_cnt[g], 1.0f);
    }
}

// ---------------- host launch ----------------
extern "C" void kernel_launch(void* const* d_in, const int* in_sizes, int n_in,
                              void* d_out, int out_size)
{
    const float* x     = (const float*)d_in[0];
    const int*   ei    = (const int*)d_in[1];
    const int*   batch = (const int*)d_in[2];
    const float* enc_W = (const float*)d_in[3];
    const float* enc_b = (const float*)d_in[4];
    const float* ln_g  = (const float*)d_in[5];
    const float* ln_b  = (const float*)d_in[6];
    const float* t     = (const float*)d_in[7];
    const float* sc    = (const float*)d_in[8];
    const float* W1    = (const float*)d_in[9];
    const float* b1    = (const float*)d_in[10];
    const float* mg    = (const float*)d_in[11];
    const float* mb    = (const float*)d_in[12];
    const float* W2    = (const float*)d_in[13];
    const float* b2    = (const float*)d_in[14];
    const float* fn_g  = (const float*)d_in[15];
    const float* fn_b  = (const float*)d_in[16];
    float* out = (float*)d_out;

    float *p_h, *p_r, *p_rn, *p_out;
    __half2* p_pq;
    cudaGetSymbolAddress((void**)&p_h,   g_h);
    cudaGetSymbolAddress((void**)&p_r,   g_r);
    cudaGetSymbolAddress((void**)&p_pq,  g_PQ);
    cudaGetSymbolAddress((void**)&p_rn,  g_rnorm);
    cudaGetSymbolAddress((void**)&p_out, g_out);

    cudaFuncSetAttribute(fused_layer_kernel,
                         cudaFuncAttributeMaxDynamicSharedMemorySize, FUSED_SMEM);

    const int MB  = (N_NODES + 63) / 64;
    const int MBF = (N_NODES + BM - 1) / BM;  // 139 blocks, one wave

    // CSR build + pool zero
    zero_kernel<<<(N_NODES + 255) / 256, 256>>>();
    csr_count_kernel<<<(N_EDGES + 255) / 256, 256>>>(ei);
    scan_kernel<<<1, 1024>>>();
    csr_fill_kernel<<<(N_EDGES + 255) / 256, 256>>>(ei);

    // encoder: h = x @ enc_W + enc_b, with fused layer-0 node_pre
    gemm_kernel<<<dim3(1, MB), 256>>>(x, enc_W, enc_b, p_h, N_NODES, HID, HID,
                                      ln_g, ln_b, t, p_r, p_pq, p_rn);

    for (int li = 0; li < N_LAYER; li++) {
        aggregate_kernel<<<(N_NODES + 7) / 8, 256>>>(sc, li);
        fused_layer_kernel<<<MBF, FTHREADS, FUSED_SMEM>>>(
            W1, b1, mg, mb, W2, b2, ln_g, ln_b, t, li, (li < N_LAYER - 1) ? 1 : 0,
            p_h, p_out, p_r, p_pq, p_rn);
    }

    final_kernel<<<N_NODES, 128>>>(fn_g, fn_b, batch);
    pool_div_kernel<<<(N_GRAPH * HID + 255) / 256, 256>>>(out);
}

// round 14
// speedup vs baseline: 1.1645x; 1.0232x over previous
#include <cuda_runtime.h>
#include <cuda_bf16.h>
#include <cuda_fp16.h>
#include <math.h>

#define N_NODES 10000
#define N_EDGES 160000
#define N_GRAPH 64
#define HID     128
#define H2      256
#define N_LAYER 14
#define BM      72            // rows per fused-layer block; grid = 139 <= 148 SMs (one wave)
#define FTHREADS 384          // 12 warps, 3 per SMSP
#define BK      32            // k-tile for both fused GEMM stages

// ---------------- device scratch (no allocations allowed) ----------------
__device__ float   g_h[N_NODES * HID];
__device__ float   g_r[N_NODES * HID];
__device__ float   g_rnorm[N_NODES];
__device__ __half2 g_PQ[N_NODES * HID];   // (P,Q) fp16 pair per feature
__device__ float   g_out[N_NODES * HID];
__device__ int     g_deg[N_NODES];
__device__ int     g_rowptr[N_NODES + 1];
__device__ int     g_cursor[N_NODES];
__device__ int     g_col[N_EDGES];
__device__ float   g_gsum[N_GRAPH * HID];
__device__ float   g_cnt[N_GRAPH];

typedef unsigned long long ull;

// ---------------- helpers ----------------
__device__ __forceinline__ ull pack2(float lo, float hi) {
    ull r;
    asm("mov.b64 %0, {%1,%2};" : "=l"(r) : "f"(lo), "f"(hi));
    return r;
}
__device__ __forceinline__ void unpack2(ull v, float& lo, float& hi) {
    asm("mov.b64 {%0,%1}, %2;" : "=f"(lo), "=f"(hi) : "l"(v));
}
#define FMA_F32X2(d, a, b, c) \
    asm("fma.rn.f32x2 %0, %1, %2, %3;" : "=l"(d) : "l"(a), "l"(b), "l"(c))

__device__ __forceinline__ void cp_async16(float* smem_dst, const float* gmem_src) {
    unsigned sa = (unsigned)__cvta_generic_to_shared(smem_dst);
    asm volatile("cp.async.cg.shared.global [%0], [%1], 16;" :: "r"(sa), "l"(gmem_src));
}
#define CP_COMMIT() asm volatile("cp.async.commit_group;")
#define CP_WAIT0()  asm volatile("cp.async.wait_group 0;")

// Programmatic Dependent Launch controls
#define GRIDDEP_WAIT()   asm volatile("griddepcontrol.wait;" ::: "memory")
#define GRIDDEP_LAUNCH() asm volatile("griddepcontrol.launch_dependents;" ::: "memory")

__device__ __forceinline__ float warpSum(float v) {
    #pragma unroll
    for (int o = 16; o; o >>= 1) v += __shfl_xor_sync(0xffffffffu, v, o);
    return v;
}
__device__ __forceinline__ float blockSum(float v, float* s) {
    #pragma unroll
    for (int o = 16; o; o >>= 1) v += __shfl_down_sync(0xffffffffu, v, o);
    __syncthreads();
    if ((threadIdx.x & 31) == 0) s[threadIdx.x >> 5] = v;
    __syncthreads();
    int nw = blockDim.x >> 5;
    float t = 0.f;
    for (int i = 0; i < nw; i++) t += s[i];
    return t;
}

// pack (p,q) float pairs into half2 lanes of a uint4
__device__ __forceinline__ uint4 packPQ(float4 pp, float4 qq) {
    __half2 h0 = __floats2half2_rn(pp.x, qq.x);
    __half2 h1 = __floats2half2_rn(pp.y, qq.y);
    __half2 h2 = __floats2half2_rn(pp.z, qq.z);
    __half2 h3 = __floats2half2_rn(pp.w, qq.w);
    uint4 u;
    u.x = *(unsigned*)&h0; u.y = *(unsigned*)&h1;
    u.z = *(unsigned*)&h2; u.w = *(unsigned*)&h3;
    return u;
}

// ---------------- zero (CSR counts + pool) ----------------
__global__ void zero_kernel() {
    int i = blockIdx.x * blockDim.x + threadIdx.x;
    if (i < N_NODES) g_deg[i] = 0;
    if (i < N_GRAPH * HID) g_gsum[i] = 0.f;
    if (i < N_GRAPH) g_cnt[i] = 0.f;
}
__global__ void csr_count_kernel(const int* __restrict__ ei) {
    int e = blockIdx.x * blockDim.x + threadIdx.x;
    if (e < N_EDGES) atomicAdd(&g_deg[ei[N_EDGES + e]], 1);
}
__global__ void scan_kernel() {
    __shared__ int s[1024];
    const int CH = 10;
    int t = threadIdx.x;
    int base = t * CH;
    int local[CH];
    int sum = 0;
    #pragma unroll
    for (int j = 0; j < CH; j++) {
        int idx = base + j;
        int v = (idx < N_NODES) ? g_deg[idx] : 0;
        local[j] = sum;
        sum += v;
    }
    s[t] = sum;
    __syncthreads();
    for (int off = 1; off < 1024; off <<= 1) {
        int v = (t >= off) ? s[t - off] : 0;
        __syncthreads();
        s[t] += v;
        __syncthreads();
    }
    int offset = (t > 0) ? s[t - 1] : 0;
    #pragma unroll
    for (int j = 0; j < CH; j++) {
        int idx = base + j;
        if (idx < N_NODES) {
            g_rowptr[idx] = offset + local[j];
            g_cursor[idx] = offset + local[j];
        }
    }
    if (t == 1023) g_rowptr[N_NODES] = s[1023];
}
__global__ void csr_fill_kernel(const int* __restrict__ ei) {
    int e = blockIdx.x * blockDim.x + threadIdx.x;
    if (e < N_EDGES) {
        int d = ei[N_EDGES + e];
        int p = atomicAdd(&g_cursor[d], 1);
        g_col[p] = ei[e];
    }
}

// ---------------- encoder GEMM: h = x @ enc_W + enc_b, fused layer-0 node_pre ------
__global__ __launch_bounds__(256) void gemm_kernel(
    const float* __restrict__ A, const float* __restrict__ B,
    const float* __restrict__ bias, float* __restrict__ Cout,
    int M, int N, int K,
    const float* __restrict__ ln_g, const float* __restrict__ ln_b,
    const float* __restrict__ tptr,
    float* __restrict__ rb, __half2* __restrict__ pqb, float* __restrict__ rnb)
{
    __shared__ float As[16][64];
    __shared__ float Bs[16][128];
    int tid = threadIdx.x;
    int bm = blockIdx.y * 64;
    int bn = blockIdx.x * 128;
    int tr = tid >> 5;
    int tc = tid & 31;
    int lane = tc;
    int row0 = tr * 8, col0 = tc * 4;

    ull acc[8][2];
    #pragma unroll
    for (int i = 0; i < 8; i++) { acc[i][0] = 0ull; acc[i][1] = 0ull; }

    int a_row = tid >> 2;
    int a_col = (tid & 3) * 4;

    for (int k0 = 0; k0 < K; k0 += 16) {
        float4 av = make_float4(0.f, 0.f, 0.f, 0.f);
        int gr = bm + a_row;
        if (gr < M) av = *(const float4*)&A[(size_t)gr * K + k0 + a_col];
        As[a_col + 0][a_row] = av.x;
        As[a_col + 1][a_row] = av.y;
        As[a_col + 2][a_row] = av.z;
        As[a_col + 3][a_row] = av.w;
        #pragma unroll
        for (int i = 0; i < 2; i++) {
            int f = tid + i * 256;
            int br = f >> 5, bc = (f & 31) * 4;
            *(float4*)&Bs[br][bc] = *(const float4*)&B[(size_t)(k0 + br) * N + bn + bc];
        }
        __syncthreads();
        #pragma unroll
        for (int k = 0; k < 16; k++) {
            float a[8];
            *(float4*)&a[0] = *(const float4*)&As[k][row0];
            *(float4*)&a[4] = *(const float4*)&As[k][row0 + 4];
            ulonglong2 bb = *(const ulonglong2*)&Bs[k][col0];
            #pragma unroll
            for (int i = 0; i < 8; i++) {
                ull aa = pack2(a[i], a[i]);
                FMA_F32X2(acc[i][0], aa, bb.x, acc[i][0]);
                FMA_F32X2(acc[i][1], aa, bb.y, acc[i][1]);
            }
        }
        __syncthreads();
    }

    int c = bn + col0;
    float4 bv = *(const float4*)&bias[c];
    float4 gv = *(const float4*)&ln_g[c];
    float4 lb = *(const float4*)&ln_b[c];
    float tval = tptr[0];
    #pragma unroll
    for (int i = 0; i < 8; i++) {
        int r = bm + row0 + i;
        if (r >= M) break;                 // r is warp-uniform: uniform break
        float v0, v1, v2, v3;
        unpack2(acc[i][0], v0, v1);
        unpack2(acc[i][1], v2, v3);
        float4 o = make_float4(v0 + bv.x, v1 + bv.y, v2 + bv.z, v3 + bv.w);
        *(float4*)&Cout[(size_t)r * N + c] = o;
        // ---- fused layer-0 node_pre (warp covers the full 128-wide row) ----
        float s1 = (o.x + o.y) + (o.z + o.w);
        float s2 = o.x * o.x + o.y * o.y + o.z * o.z + o.w * o.w;
        s1 = warpSum(s1);
        s2 = warpSum(s2);
        float mu  = s1 * (1.f / HID);
        float var = s2 * (1.f / HID) - mu * mu;
        float is  = rsqrtf(var + 1e-5f);
        float y0 = (o.x - mu) * is * gv.x + lb.x;
        float y1 = (o.y - mu) * is * gv.y + lb.y;
        float y2 = (o.z - mu) * is * gv.z + lb.z;
        float y3 = (o.w - mu) * is * gv.w + lb.w;
        float4 rr = make_float4((y0 > 0.f) ? y0 : 0.01f * y0,
                                (y1 > 0.f) ? y1 : 0.01f * y1,
                                (y2 > 0.f) ? y2 : 0.01f * y2,
                                (y3 > 0.f) ? y3 : 0.01f * y3);
        float m0 = fmaxf(y0, 0.f) + 1e-7f;
        float m1 = fmaxf(y1, 0.f) + 1e-7f;
        float m2 = fmaxf(y2, 0.f) + 1e-7f;
        float m3 = fmaxf(y3, 0.f) + 1e-7f;
        float4 qq = make_float4(expf(m0 * tval), expf(m1 * tval),
                                expf(m2 * tval), expf(m3 * tval));
        float4 pp = make_float4(m0 * qq.x, m1 * qq.y, m2 * qq.z, m3 * qq.w);
        *(float4*)&rb[(size_t)r * HID + c] = rr;
        *(uint4*)&pqb[(size_t)r * HID + c] = packPQ(pp, qq);
        float r2 = rr.x * rr.x + rr.y * rr.y + rr.z * rr.z + rr.w * rr.w;
        r2 = warpSum(r2);
        if (lane == 0) rnb[r] = sqrtf(r2);
    }
}

// ---------------- aggregation: warp-per-node, fp16 (P,Q) pairs, 4-edge unroll -----
// PDL: rowptr/col are CSR (long complete) -> prologue; wait before PQ gathers.
__global__ __launch_bounds__(256) void aggregate_kernel(
    const float* __restrict__ scptr, int li)
{
    int warp = threadIdx.x >> 5, lane = threadIdx.x & 31;
    int n = blockIdx.x * 8 + warp;
    if (n >= N_NODES) { GRIDDEP_WAIT(); return; }
    int f = lane * 4;
    int st = g_rowptr[n], en = g_rowptr[n + 1];
    GRIDDEP_WAIT();                          // predecessor (fused/gemm) writes PQ/r/rnorm
    float4 num = make_float4(0.f, 0.f, 0.f, 0.f);
    float4 den = make_float4(0.f, 0.f, 0.f, 0.f);
    int e = st;
    for (; e + 3 < en; e += 4) {
        int s0 = __ldg(&g_col[e]);
        int s1 = __ldg(&g_col[e + 1]);
        int s2 = __ldg(&g_col[e + 2]);
        int s3 = __ldg(&g_col[e + 3]);
        uint4 u0 = *(const uint4*)&g_PQ[s0 * HID + f];
        uint4 u1 = *(const uint4*)&g_PQ[s1 * HID + f];
        uint4 u2 = *(const uint4*)&g_PQ[s2 * HID + f];
        uint4 u3 = *(const uint4*)&g_PQ[s3 * HID + f];
        float2 t;
        t = __half22float2(*(__half2*)&u0.x); num.x += t.x; den.x += t.y;
        t = __half22float2(*(__half2*)&u0.y); num.y += t.x; den.y += t.y;
        t = __half22float2(*(__half2*)&u0.z); num.z += t.x; den.z += t.y;
        t = __half22float2(*(__half2*)&u0.w); num.w += t.x; den.w += t.y;
        t = __half22float2(*(__half2*)&u1.x); num.x += t.x; den.x += t.y;
        t = __half22float2(*(__half2*)&u1.y); num.y += t.x; den.y += t.y;
        t = __half22float2(*(__half2*)&u1.z); num.z += t.x; den.z += t.y;
        t = __half22float2(*(__half2*)&u1.w); num.w += t.x; den.w += t.y;
        t = __half22float2(*(__half2*)&u2.x); num.x += t.x; den.x += t.y;
        t = __half22float2(*(__half2*)&u2.y); num.y += t.x; den.y += t.y;
        t = __half22float2(*(__half2*)&u2.z); num.z += t.x; den.z += t.y;
        t = __half22float2(*(__half2*)&u2.w); num.w += t.x; den.w += t.y;
        t = __half22float2(*(__half2*)&u3.x); num.x += t.x; den.x += t.y;
        t = __half22float2(*(__half2*)&u3.y); num.y += t.x; den.y += t.y;
        t = __half22float2(*(__half2*)&u3.z); num.z += t.x; den.z += t.y;
        t = __half22float2(*(__half2*)&u3.w); num.w += t.x; den.w += t.y;
    }
    for (; e < en; e++) {
        int s0 = __ldg(&g_col[e]);
        uint4 u0 = *(const uint4*)&g_PQ[s0 * HID + f];
        float2 t;
        t = __half22float2(*(__half2*)&u0.x); num.x += t.x; den.x += t.y;
        t = __half22float2(*(__half2*)&u0.y); num.y += t.x; den.y += t.y;
        t = __half22float2(*(__half2*)&u0.z); num.z += t.x; den.z += t.y;
        t = __half22float2(*(__half2*)&u0.w); num.w += t.x; den.w += t.y;
    }
    float4 agg;
    agg.x = num.x / (den.x + 1e-16f);
    agg.y = num.y / (den.y + 1e-16f);
    agg.z = num.z / (den.z + 1e-16f);
    agg.w = num.w / (den.w + 1e-16f);
    float n2 = warpSum(agg.x * agg.x + agg.y * agg.y + agg.z * agg.z + agg.w * agg.w);
    float inv = 1.f / fmaxf(sqrtf(n2), 1e-12f);
    float coef = inv * g_rnorm[n] * scptr[li];
    float4 rv = *(const float4*)&g_r[(size_t)n * HID + f];
    float4 o = make_float4(rv.x + agg.x * coef, rv.y + agg.y * coef,
                           rv.z + agg.z * coef, rv.w + agg.w * coef);
    *(float4*)&g_out[(size_t)n * HID + f] = o;
    GRIDDEP_LAUNCH();                        // g_out fully written by this thread
}

// ---------------- fused layer: GEMM1 + LN+ReLU + GEMM2 + residual + next pre ------
// BM=72, 384 threads (12 warps, 3/SMSP), BK=32. Warp w owns rows 6w..6w+5. grid 139.
// PDL: W1 prefetch (weights, const input) is the prologue; wait before reading ob.
#define Z1_STRIDE 260
#define HS_STRIDE 132
#define ASTRIDE   76
#define AS_OFF    (BM * Z1_STRIDE)               // 18720
#define BS_OFF    (AS_OFF + 2 * BK * ASTRIDE)    // 23584
#define FUSED_SMEM ((BS_OFF + 2 * BK * 256) * 4) // 159872 bytes

__global__ void __launch_bounds__(FTHREADS) fused_layer_kernel(
    const float* __restrict__ W1, const float* __restrict__ b1,
    const float* __restrict__ mg, const float* __restrict__ mb,
    const float* __restrict__ W2, const float* __restrict__ b2,
    const float* __restrict__ ln_g, const float* __restrict__ ln_b,
    const float* __restrict__ tptr, int li, int do_pre,
    float* __restrict__ hb, const float* __restrict__ ob,
    float* __restrict__ rb, __half2* __restrict__ pqb,
    float* __restrict__ rnb)
{
    extern __shared__ float sm[];
    float* z1s = sm;                 // [72][260]
    float* As0 = sm + AS_OFF;        // double buffer [2][32][76]
    float* Bs0 = sm + BS_OFF;        // double buffer [2][32][256] (C: [2][32][128])

    const int tid  = threadIdx.x;
    const int warp = tid >> 5, lane = tid & 31;
    const int bm   = blockIdx.x * BM;
    const int row0 = warp * 6;       // 6 rows per warp
    const int c0   = lane * 4;

    // ======== Stage A: z1 = out @ W1 + b1  (72x256, K=128, BK=32) ========
    ull acc[6][4];
    #pragma unroll
    for (int i = 0; i < 6; i++)
        #pragma unroll
        for (int j = 0; j < 4; j++) acc[i][j] = 0ull;

    const float* Wl1 = W1 + (size_t)li * HID * H2;
    const int ar = tid >> 2;          // 0..95 (only <72 active)
    const int ac = (tid & 3) * 4;     // 0,4,8,12 (plus +16 for second half)
    const bool aact = (ar < BM);

    // PDL prologue: async-stage B(k0=0) = weights (independent of predecessor)
    {
        #pragma unroll
        for (int i = 0; i < 6; i++) {
            int idx = tid + i * FTHREADS;
            if (idx < 2048) cp_async16(Bs0 + idx * 4, Wl1 + idx * 4);
        }
        CP_COMMIT();
    }
    GRIDDEP_WAIT();                  // predecessor aggregate finished writing ob

    int garow = bm + ar;
    if (garow >= N_NODES) garow = N_NODES - 1;
    float4 av0 = make_float4(0.f, 0.f, 0.f, 0.f);
    float4 av1 = make_float4(0.f, 0.f, 0.f, 0.f);
    if (aact) {
        av0 = *(const float4*)&ob[(size_t)garow * HID + ac];
        av1 = *(const float4*)&ob[(size_t)garow * HID + ac + 16];
    }

    int buf = 0;
    for (int k0 = 0; k0 < HID; k0 += BK) {
        float* Asb = As0 + buf * (BK * ASTRIDE);
        float* Bsb = Bs0 + buf * (BK * 256);
        if (aact) {
            Asb[(ac + 0) * ASTRIDE + ar] = av0.x;
            Asb[(ac + 1) * ASTRIDE + ar] = av0.y;
            Asb[(ac + 2) * ASTRIDE + ar] = av0.z;
            Asb[(ac + 3) * ASTRIDE + ar] = av0.w;
            Asb[(ac + 16) * ASTRIDE + ar] = av1.x;
            Asb[(ac + 17) * ASTRIDE + ar] = av1.y;
            Asb[(ac + 18) * ASTRIDE + ar] = av1.z;
            Asb[(ac + 19) * ASTRIDE + ar] = av1.w;
        }
        CP_WAIT0();
        __syncthreads();
        if (k0 + BK < HID) {
            if (aact) {
                av0 = *(const float4*)&ob[(size_t)garow * HID + k0 + BK + ac];
                av1 = *(const float4*)&ob[(size_t)garow * HID + k0 + BK + ac + 16];
            }
            float* dst = Bs0 + (buf ^ 1) * (BK * 256);
            const float* srcb = Wl1 + (size_t)(k0 + BK) * H2;
            #pragma unroll
            for (int i = 0; i < 6; i++) {
                int idx = tid + i * FTHREADS;
                if (idx < 2048) cp_async16(dst + idx * 4, srcb + idx * 4);
            }
            CP_COMMIT();
        }
        #pragma unroll
        for (int k = 0; k < BK; k++) {
            const float* Ak = Asb + k * ASTRIDE;
            ull r01 = *(const ull*)&Ak[row0];
            ull r23 = *(const ull*)&Ak[row0 + 2];
            ull r45 = *(const ull*)&Ak[row0 + 4];
            const float* Bk = Bsb + k * 256;
            ulonglong2 bA = *(const ulonglong2*)&Bk[c0];
            ulonglong2 bB = *(const ulonglong2*)&Bk[128 + c0];
            float a[6];
            unpack2(r01, a[0], a[1]);
            unpack2(r23, a[2], a[3]);
            unpack2(r45, a[4], a[5]);
            #pragma unroll
            for (int i = 0; i < 6; i++) {
                ull aa = pack2(a[i], a[i]);
                FMA_F32X2(acc[i][0], aa, bA.x, acc[i][0]);
                FMA_F32X2(acc[i][1], aa, bA.y, acc[i][1]);
                FMA_F32X2(acc[i][2], aa, bB.x, acc[i][2]);
                FMA_F32X2(acc[i][3], aa, bB.y, acc[i][3]);
            }
        }
        buf ^= 1;
    }
    __syncthreads();

    // write z1 tile (+bias) to smem
    {
        float4 bvA = *(const float4*)&b1[(size_t)li * H2 + c0];
        float4 bvB = *(const float4*)&b1[(size_t)li * H2 + 128 + c0];
        #pragma unroll
        for (int i = 0; i < 6; i++) {
            int row = row0 + i;
            float v0, v1, v2, v3;
            unpack2(acc[i][0], v0, v1);
            unpack2(acc[i][1], v2, v3);
            float4 oA = make_float4(v0 + bvA.x, v1 + bvA.y, v2 + bvA.z, v3 + bvA.w);
            unpack2(acc[i][2], v0, v1);
            unpack2(acc[i][3], v2, v3);
            float4 oB = make_float4(v0 + bvB.x, v1 + bvB.y, v2 + bvB.z, v3 + bvB.w);
            *(float4*)&z1s[row * Z1_STRIDE + c0]       = oA;
            *(float4*)&z1s[row * Z1_STRIDE + 128 + c0] = oB;
        }
    }

    // ======== LayerNorm(256) + ReLU in smem (rows are warp-local) ========
    {
        float4 gA = *(const float4*)&mg[(size_t)li * H2 + c0];
        float4 gB = *(const float4*)&mg[(size_t)li * H2 + 128 + c0];
        float4 bA = *(const float4*)&mb[(size_t)li * H2 + c0];
        float4 bB = *(const float4*)&mb[(size_t)li * H2 + 128 + c0];
        #pragma unroll
        for (int i = 0; i < 6; i++) {
            float* rp = &z1s[(row0 + i) * Z1_STRIDE];
            float4 vA = *(const float4*)&rp[c0];
            float4 vB = *(const float4*)&rp[128 + c0];
            float s1 = (vA.x + vA.y) + (vA.z + vA.w) + (vB.x + vB.y) + (vB.z + vB.w);
            float s2 = vA.x * vA.x + vA.y * vA.y + vA.z * vA.z + vA.w * vA.w
                     + vB.x * vB.x + vB.y * vB.y + vB.z * vB.z + vB.w * vB.w;
            s1 = warpSum(s1);
            s2 = warpSum(s2);
            float mu  = s1 * (1.f / H2);
            float var = s2 * (1.f / H2) - mu * mu;
            float is  = rsqrtf(var + 1e-5f);
            vA.x = fmaxf((vA.x - mu) * is * gA.x + bA.x, 0.f);
            vA.y = fmaxf((vA.y - mu) * is * gA.y + bA.y, 0.f);
            vA.z = fmaxf((vA.z - mu) * is * gA.z + bA.z, 0.f);
            vA.w = fmaxf((vA.w - mu) * is * gA.w + bA.w, 0.f);
            vB.x = fmaxf((vB.x - mu) * is * gB.x + bB.x, 0.f);
            vB.y = fmaxf((vB.y - mu) * is * gB.y + bB.y, 0.f);
            vB.z = fmaxf((vB.z - mu) * is * gB.z + bB.z, 0.f);
            vB.w = fmaxf((vB.w - mu) * is * gB.w + bB.w, 0.f);
            *(float4*)&rp[c0]       = vA;
            *(float4*)&rp[128 + c0] = vB;
        }
    }
    __syncthreads();

    // ======== Stage C: h' = h + a @ W2 + b2  (72x128, K=256, BK=32) ========
    ull acc2[6][2];
    #pragma unroll
    for (int i = 0; i < 6; i++) { acc2[i][0] = 0ull; acc2[i][1] = 0ull; }

    const float* Wl2 = W2 + (size_t)li * H2 * HID;
    {
        #pragma unroll
        for (int i = 0; i < 3; i++) {
            int idx = tid + i * FTHREADS;
            if (idx < 1024) cp_async16(Bs0 + idx * 4, Wl2 + idx * 4);
        }
        CP_COMMIT();
    }
    buf = 0;
    for (int k0 = 0; k0 < H2; k0 += BK) {
        CP_WAIT0();
        __syncthreads();
        float* Bsb = Bs0 + buf * (BK * 128);
        if (k0 + BK < H2) {
            float* dst = Bs0 + (buf ^ 1) * (BK * 128);
            const float* srcb = Wl2 + (size_t)(k0 + BK) * HID;
            #pragma unroll
            for (int i = 0; i < 3; i++) {
                int idx = tid + i * FTHREADS;
                if (idx < 1024) cp_async16(dst + idx * 4, srcb + idx * 4);
            }
            CP_COMMIT();
        }
        #pragma unroll
        for (int k4 = 0; k4 < BK / 4; k4++) {
            float4 a4[6];
            #pragma unroll
            for (int i = 0; i < 6; i++)
                a4[i] = *(const float4*)&z1s[(row0 + i) * Z1_STRIDE + k0 + k4 * 4];
            #pragma unroll
            for (int kk = 0; kk < 4; kk++) {
                ulonglong2 bb = *(const ulonglong2*)&Bsb[(k4 * 4 + kk) * 128 + c0];
                #pragma unroll
                for (int i = 0; i < 6; i++) {
                    float avv = (kk == 0) ? a4[i].x : (kk == 1) ? a4[i].y
                              : (kk == 2) ? a4[i].z : a4[i].w;
                    ull aa = pack2(avv, avv);
                    FMA_F32X2(acc2[i][0], aa, bb.x, acc2[i][0]);
                    FMA_F32X2(acc2[i][1], aa, bb.y, acc2[i][1]);
                }
            }
        }
        buf ^= 1;
    }
    __syncthreads();   // all warps done reading z1s before hs aliases it

    // epilogue: residual add, write h, stash tile in smem (reuse z1s region)
    float* hs = sm;  // [72][132]
    {
        float4 bv = *(const float4*)&b2[(size_t)li * HID + c0];
        #pragma unroll
        for (int i = 0; i < 6; i++) {
            int row = row0 + i;
            int r = bm + row;
            float v0, v1, v2, v3;
            unpack2(acc2[i][0], v0, v1);
            unpack2(acc2[i][1], v2, v3);
            float4 o = make_float4(v0 + bv.x, v1 + bv.y, v2 + bv.z, v3 + bv.w);
            if (r < N_NODES) {
                float4 hold = *(const float4*)&hb[(size_t)r * HID + c0];
                o.x += hold.x; o.y += hold.y; o.z += hold.z; o.w += hold.w;
                *(float4*)&hb[(size_t)r * HID + c0] = o;
            }
            *(float4*)&hs[row * HS_STRIDE + c0] = o;
        }
    }

    // ======== next-layer node_pre fused (rows warp-local) ========
    if (do_pre) {
        int ln = li + 1;
        float4 gv = *(const float4*)&ln_g[(size_t)ln * HID + c0];
        float4 bb = *(const float4*)&ln_b[(size_t)ln * HID + c0];
        float t = tptr[ln];
        #pragma unroll
        for (int i = 0; i < 6; i++) {
            int row = row0 + i;
            int r = bm + row;
            if (r >= N_NODES) continue;
            float4 v = *(const float4*)&hs[row * HS_STRIDE + c0];
            float s1 = (v.x + v.y) + (v.z + v.w);
            float s2 = v.x * v.x + v.y * v.y + v.z * v.z + v.w * v.w;
            s1 = warpSum(s1);
            s2 = warpSum(s2);
            float mu  = s1 * (1.f / HID);
            float var = s2 * (1.f / HID) - mu * mu;
            float is  = rsqrtf(var + 1e-5f);
            float y0 = (v.x - mu) * is * gv.x + bb.x;
            float y1 = (v.y - mu) * is * gv.y + bb.y;
            float y2 = (v.z - mu) * is * gv.z + bb.z;
            float y3 = (v.w - mu) * is * gv.w + bb.w;
            float4 rr = make_float4((y0 > 0.f) ? y0 : 0.01f * y0,
                                    (y1 > 0.f) ? y1 : 0.01f * y1,
                                    (y2 > 0.f) ? y2 : 0.01f * y2,
                                    (y3 > 0.f) ? y3 : 0.01f * y3);
            float m0 = fmaxf(y0, 0.f) + 1e-7f;
            float m1 = fmaxf(y1, 0.f) + 1e-7f;
            float m2 = fmaxf(y2, 0.f) + 1e-7f;
            float m3 = fmaxf(y3, 0.f) + 1e-7f;
            float4 qq = make_float4(expf(m0 * t), expf(m1 * t), expf(m2 * t), expf(m3 * t));
            float4 pp = make_float4(m0 * qq.x, m1 * qq.y, m2 * qq.z, m3 * qq.w);
            *(float4*)&rb[(size_t)r * HID + c0] = rr;
            *(uint4*)&pqb[(size_t)r * HID + c0] = packPQ(pp, qq);
            float r2 = rr.x * rr.x + rr.y * rr.y + rr.z * rr.z + rr.w * rr.w;
            r2 = warpSum(r2);
            if (lane == 0) rnb[r] = sqrtf(r2);
        }
    }
    GRIDDEP_LAUNCH();                // all outputs (hb, rb, pqb, rnb) written
}

// ---------------- final LN + leaky + pooled accumulation ----------------
__global__ __launch_bounds__(128) void final_kernel(
    const float* __restrict__ fn_g, const float* __restrict__ fn_b,
    const int* __restrict__ batch)
{
    __shared__ float s[8];
    int n = blockIdx.x, f = threadIdx.x;
    int g = batch[n];                // input: independent prologue
    GRIDDEP_WAIT();                  // last fused layer wrote g_h
    float x = g_h[n * HID + f];
    float mu = blockSum(x, s) * (1.f / HID);
    float d = x - mu;
    float var = blockSum(d * d, s) * (1.f / HID);
    float y = d * rsqrtf(var + 1e-5f) * fn_g[f] + fn_b[f];
    float v = (y > 0.f) ? y : 0.01f * y;
    atomicAdd(&g_gsum[g * HID + f], v);
    if (f == 0) atomicAdd(&g_cnt[g], 1.0f);
}
__global__ void pool_div_kernel(float* __restrict__ out) {
    int i = blockIdx.x * blockDim.x + threadIdx.x;
    if (i < N_GRAPH * HID) {
        int g = i >> 7;
        out[i] = g_gsum[i] / fmaxf(g_cnt[g], 1.0f);
    }
}

// ---------------- host launch ----------------
extern "C" void kernel_launch(void* const* d_in, const int* in_sizes, int n_in,
                              void* d_out, int out_size)
{
    const float* x     = (const float*)d_in[0];
    const int*   ei    = (const int*)d_in[1];
    const int*   batch = (const int*)d_in[2];
    const float* enc_W = (const float*)d_in[3];
    const float* enc_b = (const float*)d_in[4];
    const float* ln_g  = (const float*)d_in[5];
    const float* ln_b  = (const float*)d_in[6];
    const float* t     = (const float*)d_in[7];
    const float* sc    = (const float*)d_in[8];
    const float* W1    = (const float*)d_in[9];
    const float* b1    = (const float*)d_in[10];
    const float* mg    = (const float*)d_in[11];
    const float* mb    = (const float*)d_in[12];
    const float* W2    = (const float*)d_in[13];
    const float* b2    = (const float*)d_in[14];
    const float* fn_g  = (const float*)d_in[15];
    const float* fn_b  = (const float*)d_in[16];
    float* out = (float*)d_out;

    float *p_h, *p_r, *p_rn, *p_out;
    __half2* p_pq;
    cudaGetSymbolAddress((void**)&p_h,   g_h);
    cudaGetSymbolAddress((void**)&p_r,   g_r);
    cudaGetSymbolAddress((void**)&p_pq,  g_PQ);
    cudaGetSymbolAddress((void**)&p_rn,  g_rnorm);
    cudaGetSymbolAddress((void**)&p_out, g_out);

    cudaFuncSetAttribute(fused_layer_kernel,
                         cudaFuncAttributeMaxDynamicSharedMemorySize, FUSED_SMEM);

    const int MB  = (N_NODES + 63) / 64;
    const int MBF = (N_NODES + BM - 1) / BM;  // 139 blocks, one wave

    // CSR build + pool zero
    zero_kernel<<<(N_NODES + 255) / 256, 256>>>();
    csr_count_kernel<<<(N_EDGES + 255) / 256, 256>>>(ei);
    scan_kernel<<<1, 1024>>>();
    csr_fill_kernel<<<(N_EDGES + 255) / 256, 256>>>(ei);

    // encoder: h = x @ enc_W + enc_b, with fused layer-0 node_pre
    gemm_kernel<<<dim3(1, MB), 256>>>(x, enc_W, enc_b, p_h, N_NODES, HID, HID,
                                      ln_g, ln_b, t, p_r, p_pq, p_rn);

    // PDL attribute shared by the loop launches + final
    cudaLaunchAttribute pdl[1];
    pdl[0].id = cudaLaunchAttributeProgrammaticStreamSerialization;
    pdl[0].val.programmaticStreamSerializationAllowed = 1;

    cudaLaunchConfig_t cfgA = {};
    cfgA.gridDim  = dim3((N_NODES + 7) / 8, 1, 1);
    cfgA.blockDim = dim3(256, 1, 1);
    cfgA.dynamicSmemBytes = 0;
    cfgA.stream = 0;
    cfgA.attrs = pdl;
    cfgA.numAttrs = 1;

    cudaLaunchConfig_t cfgF = {};
    cfgF.gridDim  = dim3(MBF, 1, 1);
    cfgF.blockDim = dim3(FTHREADS, 1, 1);
    cfgF.dynamicSmemBytes = FUSED_SMEM;
    cfgF.stream = 0;
    cfgF.attrs = pdl;
    cfgF.numAttrs = 1;

    for (int li = 0; li < N_LAYER; li++) {
        cudaLaunchKernelEx(&cfgA, aggregate_kernel, sc, li);
        int dp = (li < N_LAYER - 1) ? 1 : 0;
        cudaLaunchKernelEx(&cfgF, fused_layer_kernel,
                           W1, b1, mg, mb, W2, b2, ln_g, ln_b, t, li, dp,
                           p_h, (const float*)p_out, p_r, p_pq, p_rn);
    }

    cudaLaunchConfig_t cfgN = {};
    cfgN.gridDim  = dim3(N_NODES, 1, 1);
    cfgN.blockDim = dim3(128, 1, 1);
    cfgN.dynamicSmemBytes = 0;
    cfgN.stream = 0;
    cfgN.attrs = pdl;
    cfgN.numAttrs = 1;
    cudaLaunchKernelEx(&cfgN, final_kernel, fn_g, fn_b, batch);

    pool_div_kernel<<<(N_GRAPH * HID + 255) / 256, 256>>>(out);
}